// round 13
// baseline (speedup 1.0000x reference)
#include <cuda_runtime.h>
#include <cuda_bf16.h>
#include <math.h>
#include <stdint.h>

#define L_SEQ 4096
#define D_MODEL 2048
#define NH 8
#define NKVH 2
#define HD 256
#define WINDOW 512
#define NQKV 3072  // 2048 q + 512 k + 512 v

// ---------------- scratch (device globals; no cudaMalloc allowed) ----------
__device__ __nv_bfloat16 g_ah[L_SEQ * D_MODEL];        // A hi (x, later attn O)
__device__ __nv_bfloat16 g_al[L_SEQ * D_MODEL];        // A lo
__device__ __nv_bfloat16 g_wqkv_h[NQKV * D_MODEL];     // [Wq|Wk|Wv]^T hi, (N,K)
__device__ __nv_bfloat16 g_wqkv_l[NQKV * D_MODEL];
__device__ __nv_bfloat16 g_wo_h[D_MODEL * D_MODEL];    // Wo^T hi
__device__ __nv_bfloat16 g_wo_l[D_MODEL * D_MODEL];
__device__ float g_qkv[L_SEQ * NQKV];                  // fused qkv activations
// head-major split q/k/v for attention
__device__ __nv_bfloat16 g_qh[NH * L_SEQ * HD];
__device__ __nv_bfloat16 g_ql[NH * L_SEQ * HD];
__device__ __nv_bfloat16 g_kh[NKVH * L_SEQ * HD];
__device__ __nv_bfloat16 g_kl[NKVH * L_SEQ * HD];
__device__ __nv_bfloat16 g_vh[NKVH * L_SEQ * HD];
__device__ __nv_bfloat16 g_vl[NKVH * L_SEQ * HD];

static __device__ __forceinline__ uint32_t smem_u32(const void* p) {
    uint32_t a;
    asm("{ .reg .u64 t; cvta.to.shared.u64 t, %1; cvt.u32.u64 %0, t; }"
        : "=r"(a) : "l"(p));
    return a;
}

#define CPA16(dst, src)                                                        \
    asm volatile("cp.async.cg.shared.global [%0], [%1], 16;"                   \
                 :: "r"(dst), "l"(src) : "memory")
#define CPA_COMMIT asm volatile("cp.async.commit_group;" ::: "memory")
#define CPA_WAIT0  asm volatile("cp.async.wait_group 0;" ::: "memory")
#define CPA_WAIT1  asm volatile("cp.async.wait_group 1;" ::: "memory")

#define LDM4(r, addr)                                                          \
    asm volatile("ldmatrix.sync.aligned.m8n8.x4.shared.b16 {%0,%1,%2,%3}, [%4];"\
        : "=r"((r)[0]), "=r"((r)[1]), "=r"((r)[2]), "=r"((r)[3]) : "r"(addr))

#define LDM4T(r, addr)                                                         \
    asm volatile("ldmatrix.sync.aligned.m8n8.x4.trans.shared.b16 {%0,%1,%2,%3}, [%4];"\
        : "=r"((r)[0]), "=r"((r)[1]), "=r"((r)[2]), "=r"((r)[3]) : "r"(addr))

#define MMA16816(c, a, b0v, b1v)                                               \
    asm volatile("mma.sync.aligned.m16n8k16.row.col.f32.bf16.bf16.f32 "        \
        "{%0,%1,%2,%3}, {%4,%5,%6,%7}, {%8,%9}, {%0,%1,%2,%3};"                \
        : "+f"((c)[0]), "+f"((c)[1]), "+f"((c)[2]), "+f"((c)[3])               \
        : "r"((a)[0]), "r"((a)[1]), "r"((a)[2]), "r"((a)[3]),                  \
          "r"(b0v), "r"(b1v))

// ---------------- split fp32 -> bf16 hi/lo (vector x4) ---------------------
__global__ void split_kernel(const float* __restrict__ in,
                             __nv_bfloat16* __restrict__ hi,
                             __nv_bfloat16* __restrict__ lo, int n4) {
    int i = blockIdx.x * blockDim.x + threadIdx.x;
    if (i >= n4) return;
    float4 a = ((const float4*)in)[i];
    __nv_bfloat16 h0 = __float2bfloat16(a.x);
    __nv_bfloat16 h1 = __float2bfloat16(a.y);
    __nv_bfloat16 h2 = __float2bfloat16(a.z);
    __nv_bfloat16 h3 = __float2bfloat16(a.w);
    __nv_bfloat16 l0 = __float2bfloat16(a.x - __bfloat162float(h0));
    __nv_bfloat16 l1 = __float2bfloat16(a.y - __bfloat162float(h1));
    __nv_bfloat16 l2 = __float2bfloat16(a.z - __bfloat162float(h2));
    __nv_bfloat16 l3 = __float2bfloat16(a.w - __bfloat162float(h3));
    __nv_bfloat162* ph = (__nv_bfloat162*)hi;
    __nv_bfloat162* pl = (__nv_bfloat162*)lo;
    ph[i * 2]     = __nv_bfloat162{h0, h1};
    ph[i * 2 + 1] = __nv_bfloat162{h2, h3};
    pl[i * 2]     = __nv_bfloat162{l0, l1};
    pl[i * 2 + 1] = __nv_bfloat162{l2, l3};
}

// ---------------- fused transpose+split of all weights ---------------------
// blockIdx.x ranges: [0,64) Wq | [64,80) Wk | [80,96) Wv | [96,160) Wo
__global__ void tsplit_all(const float* __restrict__ Wq, const float* __restrict__ Wk,
                           const float* __restrict__ Wv, const float* __restrict__ Wo,
                           __nv_bfloat16* __restrict__ wqh, __nv_bfloat16* __restrict__ wql,
                           __nv_bfloat16* __restrict__ woh, __nv_bfloat16* __restrict__ wol) {
    __shared__ float s[32][33];
    int bx = blockIdx.x;
    const float* W; __nv_bfloat16 *th, *tl; int N, roff;
    if (bx < 64)      { W = Wq; N = 2048; roff = 0;    th = wqh; tl = wql; }
    else if (bx < 80) { W = Wk; N = 512;  roff = 2048; th = wqh; tl = wql; bx -= 64; }
    else if (bx < 96) { W = Wv; N = 512;  roff = 2560; th = wqh; tl = wql; bx -= 80; }
    else              { W = Wo; N = 2048; roff = 0;    th = woh; tl = wol; bx -= 96; }

    int n0 = bx * 32, k0 = blockIdx.y * 32;
    int tx = threadIdx.x, ty = threadIdx.y;  // 32 x 8
#pragma unroll
    for (int r = 0; r < 4; r++)
        s[ty + r * 8][tx] = W[(size_t)(k0 + ty + r * 8) * N + n0 + tx];
    __syncthreads();
#pragma unroll
    for (int r = 0; r < 4; r++) {
        int n = n0 + ty + r * 8;
        float a = s[tx][ty + r * 8];
        __nv_bfloat16 h = __float2bfloat16(a);
        __nv_bfloat16 l = __float2bfloat16(a - __bfloat162float(h));
        th[(size_t)(roff + n) * D_MODEL + k0 + tx] = h;
        tl[(size_t)(roff + n) * D_MODEL + k0 + tx] = l;
    }
}

// ---------------- HMMA bf16x3 GEMM: C[M,N] = A @ B^T ------------------------
#define GOP_B 8192
#define GBUF_B (4 * GOP_B)
#define GEMM_SMEM (3 * GBUF_B)  // 96KB

#define GSW(row, g) (((row) << 6) + ((((g) ^ (((row) >> 1) & 3)) << 4)))

__global__ void __launch_bounds__(256, 2)
gemm_hmma(const __nv_bfloat16* __restrict__ Ah, const __nv_bfloat16* __restrict__ Al,
          const __nv_bfloat16* __restrict__ Bh, const __nv_bfloat16* __restrict__ Bl,
          float* __restrict__ C, int K, int ldc) {
    extern __shared__ __align__(128) char gsm[];
    const int tid = threadIdx.x;
    const int lane = tid & 31;
    const int wid = tid >> 5;
    const int wm = (wid & 1) * 64;
    const int wn = (wid >> 1) * 32;
    const int bm = blockIdx.y * 128;
    const int bn = blockIdx.x * 128;
    const uint32_t sbase = smem_u32(gsm);

    const __nv_bfloat16* gptr[4] = {
        Ah + (size_t)bm * K, Al + (size_t)bm * K,
        Bh + (size_t)bn * K, Bl + (size_t)bn * K };

    // hoisted per-thread staging addresses (chunk-invariant)
    const __nv_bfloat16* srcb[8];
    uint32_t dstoff[8];
#pragma unroll
    for (int it = 0; it < 8; it++) {
        int s = it * 256 + tid;
        int op = s >> 9, t = s & 511;
        int row = t >> 2, cc = t & 3;
        srcb[it] = gptr[op] + (size_t)row * K + cc * 8;
        dstoff[it] = op * GOP_B + GSW(row, cc);
    }

    float acc[4][4][4];
#pragma unroll
    for (int a = 0; a < 4; a++)
#pragma unroll
        for (int b = 0; b < 4; b++)
#pragma unroll
            for (int c = 0; c < 4; c++) acc[a][b][c] = 0.f;

    const int a_row_l = lane & 15;
    const int a_gs = lane >> 4;
    const int b_row_l = ((lane & 16) ? 8 : 0) + (lane & 7);
    const int b_gs = (lane >> 3) & 1;

    const int nch = K >> 5;

    auto stage = [&](int c) {
        const int k0 = c << 5;
        const uint32_t dbase = sbase + (uint32_t)(c % 3) * GBUF_B;
#pragma unroll
        for (int it = 0; it < 8; it++)
            CPA16(dbase + dstoff[it], srcb[it] + k0);
        CPA_COMMIT;
    };

    stage(0);
    if (nch > 1) stage(1);

    for (int c = 0; c < nch; c++) {
        if (c + 1 < nch) { CPA_WAIT1; } else { CPA_WAIT0; }
        __syncthreads();
        if (c + 2 < nch) stage(c + 2);

        const uint32_t dbase = sbase + (uint32_t)(c % 3) * GBUF_B;
#pragma unroll
        for (int ks = 0; ks < 2; ks++) {
            const int kb2 = ks * 2;
            uint32_t bhf[2][4], blf[2][4];
#pragma unroll
            for (int np = 0; np < 2; np++) {
                int rb = wn + np * 16 + b_row_l;
                uint32_t offb = GSW(rb, kb2 + b_gs);
                LDM4(bhf[np], dbase + 2 * GOP_B + offb);
                LDM4(blf[np], dbase + 3 * GOP_B + offb);
            }
#pragma unroll
            for (int mt = 0; mt < 4; mt++) {
                uint32_t ahf[4], alf[4];
                int ra = wm + mt * 16 + a_row_l;
                uint32_t offa = GSW(ra, kb2 + a_gs);
                LDM4(ahf, dbase + offa);
                LDM4(alf, dbase + GOP_B + offa);
#pragma unroll
                for (int nt = 0; nt < 4; nt++) {
                    const int np = nt >> 1, sel = (nt & 1) * 2;
                    MMA16816(acc[mt][nt], ahf, bhf[np][sel], bhf[np][sel + 1]);
                    MMA16816(acc[mt][nt], ahf, blf[np][sel], blf[np][sel + 1]);
                    MMA16816(acc[mt][nt], alf, bhf[np][sel], bhf[np][sel + 1]);
                }
            }
        }
    }

#pragma unroll
    for (int mt = 0; mt < 4; mt++) {
        int r0 = bm + wm + mt * 16 + (lane >> 2);
#pragma unroll
        for (int nt = 0; nt < 4; nt++) {
            int c0 = bn + wn + nt * 8 + (lane & 3) * 2;
            *(float2*)(C + (size_t)r0 * ldc + c0) =
                make_float2(acc[mt][nt][0], acc[mt][nt][1]);
            *(float2*)(C + (size_t)(r0 + 8) * ldc + c0) =
                make_float2(acc[mt][nt][2], acc[mt][nt][3]);
        }
    }
}

// ---------------- fused RMS norm (+scale, +RoPE) -> split bf16 head-major --
// timescale via exp2f; sincosf shares one range reduction (accuracy = libm)
#define LOG2_BASE 13.287712379549449f

__global__ void norm_split_all(const float* __restrict__ qkv,
                               const float* __restrict__ q_scale,
                               const float* __restrict__ k_scale,
                               const int* __restrict__ positions,
                               __nv_bfloat16* __restrict__ qh, __nv_bfloat16* __restrict__ ql,
                               __nv_bfloat16* __restrict__ kh, __nv_bfloat16* __restrict__ kl,
                               __nv_bfloat16* __restrict__ vh, __nv_bfloat16* __restrict__ vl) {
    const int l = blockIdx.x;
    const int slot = blockIdx.y;   // 0..11
    int headoff, hh, do_rope;
    const float* scale;
    __nv_bfloat16 *oh, *ol;
    if (slot < 8)       { headoff = 0;    hh = slot;      scale = q_scale; do_rope = 1; oh = qh; ol = ql; }
    else if (slot < 10) { headoff = 2048; hh = slot - 8;  scale = k_scale; do_rope = 1; oh = kh; ol = kl; }
    else                { headoff = 2560; hh = slot - 10; scale = nullptr; do_rope = 0; oh = vh; ol = vl; }

    const float* p = qkv + (size_t)l * NQKV + headoff + hh * HD;
    const int t = threadIdx.x;  // 0..127
    const int lane = t & 31;
    const int wid = t >> 5;

    float a = p[t];
    float b = p[t + 128];
    float ss = a * a + b * b;
#pragma unroll
    for (int off = 16; off > 0; off >>= 1)
        ss += __shfl_xor_sync(0xffffffffu, ss, off);
    __shared__ float red[4];
    if (lane == 0) red[wid] = ss;
    __syncthreads();
    float total = red[0] + red[1] + red[2] + red[3];
    float inv = rsqrtf(total * (1.0f / HD) + 1e-6f);

    float xa = a * inv, xb = b * inv;
    if (scale) { xa *= scale[t]; xb *= scale[t + 128]; }

    float ya, yb;
    if (do_rope) {
        float pos = (float)positions[l];
        float ts = exp2f((2.0f * (float)t / (float)HD) * LOG2_BASE);
        float ang = pos / ts;
        float sn, cs;
        sincosf(ang, &sn, &cs);
        ya = xa * cs - xb * sn;
        yb = xb * cs + xa * sn;
    } else {
        ya = xa; yb = xb;
    }
    size_t o = ((size_t)hh * L_SEQ + l) * HD;
    __nv_bfloat16 ha = __float2bfloat16(ya);
    __nv_bfloat16 hb = __float2bfloat16(yb);
    oh[o + t]       = ha;
    oh[o + t + 128] = hb;
    ol[o + t]       = __float2bfloat16(ya - __bfloat162float(ha));
    ol[o + t + 128] = __float2bfloat16(yb - __bfloat162float(hb));
}

// ---------------- tensor-core sliding-window flash attention ---------------
// Pipelined K (double-buffer) / V (single) staging; 112KB smem, 2 CTAs/SM.
// Per-warp skip of fully-out-of-window K-tiles (barriers stay uniform).
#define QB 64
#define KT 16
#define ATT_SMEM (112 * 1024)

__global__ void __launch_bounds__(256, 2)
attn_tc(const __nv_bfloat16* __restrict__ qhp, const __nv_bfloat16* __restrict__ qlp,
        const __nv_bfloat16* __restrict__ khp, const __nv_bfloat16* __restrict__ klp,
        const __nv_bfloat16* __restrict__ vhp, const __nv_bfloat16* __restrict__ vlp,
        __nv_bfloat16* __restrict__ oh, __nv_bfloat16* __restrict__ ol) {
    extern __shared__ __align__(128) char asmem[];
    const int tid = threadIdx.x, lane = tid & 31, wid = tid >> 5;
    const int qb = blockIdx.x, h = blockIdx.y;
    const int kvh = h / (NH / NKVH);
    const int Q0 = qb * QB;
    const int qg = wid >> 1;
    const int dh = wid & 1;
    const uint32_t sb = smem_u32(asmem);
    const uint32_t sQ = sb;                     // hi; lo at +32768
    const uint32_t sK = sb + 65536;             // buf b at + b*16384 (Kh | Kl+8192)
    const uint32_t sV = sb + 98304;             // Vh | Vl+8192

    const __nv_bfloat16* kbh = khp + (size_t)kvh * L_SEQ * HD;
    const __nv_bfloat16* kbl = klp + (size_t)kvh * L_SEQ * HD;
    const __nv_bfloat16* vbh = vhp + (size_t)kvh * L_SEQ * HD;
    const __nv_bfloat16* vbl = vlp + (size_t)kvh * L_SEQ * HD;

    auto stage_tile = [&](const __nv_bfloat16* mh, const __nv_bfloat16* ml,
                          int kt, uint32_t dbase) {
#pragma unroll
        for (int r = 0; r < 4; r++) {
            int gid = r * 256 + tid;
            int mat = gid >> 9;
            int t = gid & 511;
            int row = t >> 5, g = t & 31;
            const __nv_bfloat16* src = (mat ? ml : mh) + (size_t)(kt + row) * HD + g * 8;
            uint32_t dst = dbase + mat * 8192 + row * 512 + ((g ^ (row & 7)) << 4);
            CPA16(dst, src);
        }
        CPA_COMMIT;
    };

    // ---- stage Q, then K0, then V0 (three groups)
#pragma unroll
    for (int i = 0; i < 16; i++) {
        int gid = i * 256 + tid;
        int mat = gid >> 11;
        int t = gid & 2047;
        int row = t >> 5, g = t & 31;
        const __nv_bfloat16* src = (mat ? qlp : qhp)
            + ((size_t)h * L_SEQ + Q0 + row) * HD + g * 8;
        uint32_t dst = sQ + mat * 32768 + row * 512 + ((g ^ (row & 7)) << 4);
        CPA16(dst, src);
    }
    CPA_COMMIT;

    int kstart = Q0 - (WINDOW - 1);
    if (kstart < 0) kstart = 0;
    kstart &= ~(KT - 1);
    const int kend = Q0 + QB;
    const int R0 = Q0 + qg * 16;

    stage_tile(kbh, kbl, kstart, sK);       // K0 -> buf 0
    stage_tile(vbh, vbl, kstart, sV);       // V0
    CPA_WAIT0;
    __syncthreads();

    float m0 = -1e9f, m1 = -1e9f;
    float l0 = 0.f, l1 = 0.f;
    float O[16][4];
#pragma unroll
    for (int nt = 0; nt < 16; nt++)
#pragma unroll
        for (int e = 0; e < 4; e++) O[nt][e] = 0.f;

    const int qa_r = ((lane >> 3) & 1) * 8 + (lane & 7);
    const int qa_gs = (lane >> 4);
    const int kb_r = ((lane >> 4) & 1) * 8 + (lane & 7);
    const int kb_gs = ((lane >> 3) & 1);
    const int vb_r = ((lane >> 3) & 1) * 8 + (lane & 7);
    const int vb_gs = (lane >> 4);

    int buf = 0;
    for (int kt = kstart; kt < kend; kt += KT, buf ^= 1) {
        const bool has_next = (kt + KT < kend);
        const uint32_t kB = sK + buf * 16384;
        // per-warp tile liveness: any (q in [R0,R0+15], k in [kt,kt+15]) valid?
        const bool active = (kt <= R0 + 15) && (kt + KT - 1 >= R0 - (WINDOW - 1));

        float S[2][4];
#pragma unroll
        for (int nt = 0; nt < 2; nt++)
#pragma unroll
            for (int e = 0; e < 4; e++) S[nt][e] = 0.f;

        if (active) {
#pragma unroll
            for (int ks = 0; ks < 16; ks++) {
                uint32_t qa[4], qal[4], kf[4], kfl[4];
                int qrow = qg * 16 + qa_r;
                int qg_g = ks * 2 + qa_gs;
                uint32_t qaddr = sQ + qrow * 512 + (((qg_g) ^ (qrow & 7)) << 4);
                LDM4(qa, qaddr);
                LDM4(qal, qaddr + 32768);
                int kg_g = ks * 2 + kb_gs;
                uint32_t kaddr = kB + kb_r * 512 + (((kg_g) ^ (kb_r & 7)) << 4);
                LDM4(kf, kaddr);
                LDM4(kfl, kaddr + 8192);
                MMA16816(S[0], qa, kf[0], kf[1]);
                MMA16816(S[0], qa, kfl[0], kfl[1]);
                MMA16816(S[0], qal, kf[0], kf[1]);
                MMA16816(S[1], qa, kf[2], kf[3]);
                MMA16816(S[1], qa, kfl[2], kfl[3]);
                MMA16816(S[1], qal, kf[2], kf[3]);
            }
        }

        if (has_next) stage_tile(kbh, kbl, kt + KT, sK + (buf ^ 1) * 16384);

        if (has_next) { CPA_WAIT1; } else { CPA_WAIT0; }
        __syncthreads();

        if (active) {
            const bool fullvalid = (kt + KT - 1 <= R0) && (kt >= R0 + 15 - (WINDOW - 1));
            if (!fullvalid) {
                int rq0 = R0 + (lane >> 2);
                int ck = kt + (lane & 3) * 2;
#pragma unroll
                for (int nt = 0; nt < 2; nt++)
#pragma unroll
                    for (int e = 0; e < 4; e++) {
                        int q = rq0 + ((e >= 2) ? 8 : 0);
                        int k = ck + nt * 8 + (e & 1);
                        if (k > q || k < q - (WINDOW - 1)) S[nt][e] = -1e30f;
                    }
            }

            float tm0 = fmaxf(fmaxf(S[0][0], S[0][1]), fmaxf(S[1][0], S[1][1]));
            float tm1 = fmaxf(fmaxf(S[0][2], S[0][3]), fmaxf(S[1][2], S[1][3]));
            tm0 = fmaxf(tm0, __shfl_xor_sync(0xffffffffu, tm0, 1));
            tm0 = fmaxf(tm0, __shfl_xor_sync(0xffffffffu, tm0, 2));
            tm1 = fmaxf(tm1, __shfl_xor_sync(0xffffffffu, tm1, 1));
            tm1 = fmaxf(tm1, __shfl_xor_sync(0xffffffffu, tm1, 2));
            float mn0 = fmaxf(m0, tm0), mn1 = fmaxf(m1, tm1);
            float sc0 = __expf(m0 - mn0), sc1 = __expf(m1 - mn1);
            m0 = mn0; m1 = mn1;

            float p[2][4];
#pragma unroll
            for (int nt = 0; nt < 2; nt++) {
                p[nt][0] = __expf(S[nt][0] - mn0);
                p[nt][1] = __expf(S[nt][1] - mn0);
                p[nt][2] = __expf(S[nt][2] - mn1);
                p[nt][3] = __expf(S[nt][3] - mn1);
            }
            float rs0 = p[0][0] + p[0][1] + p[1][0] + p[1][1];
            float rs1 = p[0][2] + p[0][3] + p[1][2] + p[1][3];
            rs0 += __shfl_xor_sync(0xffffffffu, rs0, 1);
            rs0 += __shfl_xor_sync(0xffffffffu, rs0, 2);
            rs1 += __shfl_xor_sync(0xffffffffu, rs1, 1);
            rs1 += __shfl_xor_sync(0xffffffffu, rs1, 2);
            l0 = l0 * sc0 + rs0;
            l1 = l1 * sc1 + rs1;

#pragma unroll
            for (int nt = 0; nt < 16; nt++) {
                O[nt][0] *= sc0; O[nt][1] *= sc0;
                O[nt][2] *= sc1; O[nt][3] *= sc1;
            }

            uint32_t pa[4], pal[4];
#pragma unroll
            for (int e = 0; e < 4; e++) {
                int nt = e >> 1, half = (e & 1) * 2;
                float v0 = p[nt][half], v1 = p[nt][half + 1];
                __nv_bfloat16 h0 = __float2bfloat16(v0);
                __nv_bfloat16 h1 = __float2bfloat16(v1);
                __nv_bfloat162 hh2{h0, h1};
                __nv_bfloat162 ll2{__float2bfloat16(v0 - __bfloat162float(h0)),
                                   __float2bfloat16(v1 - __bfloat162float(h1))};
                pa[e] = *(uint32_t*)&hh2;
                pal[e] = *(uint32_t*)&ll2;
            }

#pragma unroll
            for (int j = 0; j < 8; j++) {
                uint32_t vf[4], vfl[4];
                int vg = dh * 16 + j * 2 + vb_gs;
                uint32_t vaddr = sV + vb_r * 512 + (((vg) ^ (vb_r & 7)) << 4);
                LDM4T(vf, vaddr);
                LDM4T(vfl, vaddr + 8192);
                MMA16816(O[2 * j], pa, vf[0], vf[1]);
                MMA16816(O[2 * j], pa, vfl[0], vfl[1]);
                MMA16816(O[2 * j], pal, vf[0], vf[1]);
                MMA16816(O[2 * j + 1], pa, vf[2], vf[3]);
                MMA16816(O[2 * j + 1], pa, vfl[2], vfl[3]);
                MMA16816(O[2 * j + 1], pal, vf[2], vf[3]);
            }
        }

        if (has_next) {
            __syncthreads();                       // PV readers done; V buffer free
            stage_tile(vbh, vbl, kt + KT, sV);     // pending: [K_{i+1}, V_{i+1}]
            CPA_WAIT1;                             // K_{i+1} done
            __syncthreads();                       // K_{i+1} visible to all
        }
    }

    float il0 = 1.0f / l0, il1 = 1.0f / l1;
    int row0 = Q0 + qg * 16 + (lane >> 2);
#pragma unroll
    for (int nt = 0; nt < 16; nt++) {
        int n = dh * 128 + nt * 8 + (lane & 3) * 2;
        size_t base0 = (size_t)row0 * D_MODEL + h * HD + n;
        size_t base1 = (size_t)(row0 + 8) * D_MODEL + h * HD + n;
        float v0 = O[nt][0] * il0, v1 = O[nt][1] * il0;
        float v2 = O[nt][2] * il1, v3 = O[nt][3] * il1;
        __nv_bfloat16 h0 = __float2bfloat16(v0), h1 = __float2bfloat16(v1);
        __nv_bfloat16 h2 = __float2bfloat16(v2), h3 = __float2bfloat16(v3);
        *(__nv_bfloat162*)(oh + base0) = __nv_bfloat162{h0, h1};
        *(__nv_bfloat162*)(oh + base1) = __nv_bfloat162{h2, h3};
        *(__nv_bfloat162*)(ol + base0) =
            __nv_bfloat162{__float2bfloat16(v0 - __bfloat162float(h0)),
                           __float2bfloat16(v1 - __bfloat162float(h1))};
        *(__nv_bfloat162*)(ol + base1) =
            __nv_bfloat162{__float2bfloat16(v2 - __bfloat162float(h2)),
                           __float2bfloat16(v3 - __bfloat162float(h3))};
    }
}

// ---------------------------------------------------------------------------
extern "C" void kernel_launch(void* const* d_in, const int* in_sizes, int n_in,
                              void* d_out, int out_size) {
    const float* x       = (const float*)d_in[0];
    const int* positions = (const int*)d_in[1];
    const float* Wq      = (const float*)d_in[2];
    const float* Wk      = (const float*)d_in[3];
    const float* Wv      = (const float*)d_in[4];
    const float* Wo      = (const float*)d_in[5];
    const float* q_scale = (const float*)d_in[6];
    const float* k_scale = (const float*)d_in[7];
    float* out           = (float*)d_out;

    __nv_bfloat16 *ah, *al, *wqh, *wql, *woh, *wol, *qh, *ql, *kh, *kl, *vh, *vl;
    float* qkv;
    cudaGetSymbolAddress((void**)&ah, g_ah);
    cudaGetSymbolAddress((void**)&al, g_al);
    cudaGetSymbolAddress((void**)&wqh, g_wqkv_h);
    cudaGetSymbolAddress((void**)&wql, g_wqkv_l);
    cudaGetSymbolAddress((void**)&woh, g_wo_h);
    cudaGetSymbolAddress((void**)&wol, g_wo_l);
    cudaGetSymbolAddress((void**)&qh, g_qh);
    cudaGetSymbolAddress((void**)&ql, g_ql);
    cudaGetSymbolAddress((void**)&kh, g_kh);
    cudaGetSymbolAddress((void**)&kl, g_kl);
    cudaGetSymbolAddress((void**)&vh, g_vh);
    cudaGetSymbolAddress((void**)&vl, g_vl);
    cudaGetSymbolAddress((void**)&qkv, g_qkv);

    cudaFuncSetAttribute(gemm_hmma, cudaFuncAttributeMaxDynamicSharedMemorySize,
                         GEMM_SMEM);
    cudaFuncSetAttribute(attn_tc, cudaFuncAttributeMaxDynamicSharedMemorySize,
                         ATT_SMEM);

    // fused weight transpose+split (one launch)
    tsplit_all<<<dim3(160, 64), dim3(32, 8)>>>(Wq, Wk, Wv, Wo, wqh, wql, woh, wol);

    // activations: bf16 split
    int n4 = (L_SEQ * D_MODEL) / 4;
    split_kernel<<<(n4 + 255) / 256, 256>>>(x, ah, al, n4);

    // fused QKV projection
    gemm_hmma<<<dim3(NQKV / 128, L_SEQ / 128), 256, GEMM_SMEM>>>(
        ah, al, wqh, wql, qkv, D_MODEL, NQKV);

    // fused norm (+rope) + split
    norm_split_all<<<dim3(L_SEQ, 12), 128>>>(qkv, q_scale, k_scale, positions,
                                             qh, ql, kh, kl, vh, vl);

    // pipelined tensor-core attention; writes split O into ah/al
    attn_tc<<<dim3(L_SEQ / QB, NH), 256, ATT_SMEM>>>(qh, ql, kh, kl, vh, vl, ah, al);

    // output projection
    gemm_hmma<<<dim3(D_MODEL / 128, L_SEQ / 128), 256, GEMM_SMEM>>>(
        ah, al, woh, wol, out, D_MODEL, D_MODEL);
}

// round 14
// speedup vs baseline: 1.5248x; 1.5248x over previous
#include <cuda_runtime.h>
#include <cuda_bf16.h>
#include <math.h>
#include <stdint.h>

#define L_SEQ 4096
#define D_MODEL 2048
#define NH 8
#define NKVH 2
#define HD 256
#define WINDOW 512
#define NQKV 3072  // 2048 q + 512 k + 512 v

// ---------------- scratch (device globals; no cudaMalloc allowed) ----------
__device__ __nv_bfloat16 g_ah[L_SEQ * D_MODEL];        // A hi (x, later attn O)
__device__ __nv_bfloat16 g_al[L_SEQ * D_MODEL];        // A lo
__device__ __nv_bfloat16 g_wqkv_h[NQKV * D_MODEL];     // [Wq|Wk|Wv]^T hi, (N,K)
__device__ __nv_bfloat16 g_wqkv_l[NQKV * D_MODEL];
__device__ __nv_bfloat16 g_wo_h[D_MODEL * D_MODEL];    // Wo^T hi
__device__ __nv_bfloat16 g_wo_l[D_MODEL * D_MODEL];
__device__ float g_qkv[L_SEQ * NQKV];                  // fused qkv activations
// head-major split q/k/v for attention
__device__ __nv_bfloat16 g_qh[NH * L_SEQ * HD];
__device__ __nv_bfloat16 g_ql[NH * L_SEQ * HD];
__device__ __nv_bfloat16 g_kh[NKVH * L_SEQ * HD];
__device__ __nv_bfloat16 g_kl[NKVH * L_SEQ * HD];
__device__ __nv_bfloat16 g_vh[NKVH * L_SEQ * HD];
__device__ __nv_bfloat16 g_vl[NKVH * L_SEQ * HD];

static __device__ __forceinline__ uint32_t smem_u32(const void* p) {
    uint32_t a;
    asm("{ .reg .u64 t; cvta.to.shared.u64 t, %1; cvt.u32.u64 %0, t; }"
        : "=r"(a) : "l"(p));
    return a;
}

#define CPA16(dst, src)                                                        \
    asm volatile("cp.async.cg.shared.global [%0], [%1], 16;"                   \
                 :: "r"(dst), "l"(src) : "memory")
#define CPA_COMMIT asm volatile("cp.async.commit_group;" ::: "memory")
#define CPA_WAIT0  asm volatile("cp.async.wait_group 0;" ::: "memory")
#define CPA_WAIT1  asm volatile("cp.async.wait_group 1;" ::: "memory")

#define LDM4(r, addr)                                                          \
    asm volatile("ldmatrix.sync.aligned.m8n8.x4.shared.b16 {%0,%1,%2,%3}, [%4];"\
        : "=r"((r)[0]), "=r"((r)[1]), "=r"((r)[2]), "=r"((r)[3]) : "r"(addr))

#define LDM4T(r, addr)                                                         \
    asm volatile("ldmatrix.sync.aligned.m8n8.x4.trans.shared.b16 {%0,%1,%2,%3}, [%4];"\
        : "=r"((r)[0]), "=r"((r)[1]), "=r"((r)[2]), "=r"((r)[3]) : "r"(addr))

#define MMA16816(c, a, b0v, b1v)                                               \
    asm volatile("mma.sync.aligned.m16n8k16.row.col.f32.bf16.bf16.f32 "        \
        "{%0,%1,%2,%3}, {%4,%5,%6,%7}, {%8,%9}, {%0,%1,%2,%3};"                \
        : "+f"((c)[0]), "+f"((c)[1]), "+f"((c)[2]), "+f"((c)[3])               \
        : "r"((a)[0]), "r"((a)[1]), "r"((a)[2]), "r"((a)[3]),                  \
          "r"(b0v), "r"(b1v))

// ---------------- split fp32 -> bf16 hi/lo (vector x4) ---------------------
__global__ void split_kernel(const float* __restrict__ in,
                             __nv_bfloat16* __restrict__ hi,
                             __nv_bfloat16* __restrict__ lo, int n4) {
    int i = blockIdx.x * blockDim.x + threadIdx.x;
    if (i >= n4) return;
    float4 a = ((const float4*)in)[i];
    __nv_bfloat16 h0 = __float2bfloat16(a.x);
    __nv_bfloat16 h1 = __float2bfloat16(a.y);
    __nv_bfloat16 h2 = __float2bfloat16(a.z);
    __nv_bfloat16 h3 = __float2bfloat16(a.w);
    __nv_bfloat16 l0 = __float2bfloat16(a.x - __bfloat162float(h0));
    __nv_bfloat16 l1 = __float2bfloat16(a.y - __bfloat162float(h1));
    __nv_bfloat16 l2 = __float2bfloat16(a.z - __bfloat162float(h2));
    __nv_bfloat16 l3 = __float2bfloat16(a.w - __bfloat162float(h3));
    __nv_bfloat162* ph = (__nv_bfloat162*)hi;
    __nv_bfloat162* pl = (__nv_bfloat162*)lo;
    ph[i * 2]     = __nv_bfloat162{h0, h1};
    ph[i * 2 + 1] = __nv_bfloat162{h2, h3};
    pl[i * 2]     = __nv_bfloat162{l0, l1};
    pl[i * 2 + 1] = __nv_bfloat162{l2, l3};
}

// ---------------- fused transpose+split of all weights ---------------------
// blockIdx.x ranges: [0,64) Wq | [64,80) Wk | [80,96) Wv | [96,160) Wo
__global__ void tsplit_all(const float* __restrict__ Wq, const float* __restrict__ Wk,
                           const float* __restrict__ Wv, const float* __restrict__ Wo,
                           __nv_bfloat16* __restrict__ wqh, __nv_bfloat16* __restrict__ wql,
                           __nv_bfloat16* __restrict__ woh, __nv_bfloat16* __restrict__ wol) {
    __shared__ float s[32][33];
    int bx = blockIdx.x;
    const float* W; __nv_bfloat16 *th, *tl; int N, roff;
    if (bx < 64)      { W = Wq; N = 2048; roff = 0;    th = wqh; tl = wql; }
    else if (bx < 80) { W = Wk; N = 512;  roff = 2048; th = wqh; tl = wql; bx -= 64; }
    else if (bx < 96) { W = Wv; N = 512;  roff = 2560; th = wqh; tl = wql; bx -= 80; }
    else              { W = Wo; N = 2048; roff = 0;    th = woh; tl = wol; bx -= 96; }

    int n0 = bx * 32, k0 = blockIdx.y * 32;
    int tx = threadIdx.x, ty = threadIdx.y;  // 32 x 8
#pragma unroll
    for (int r = 0; r < 4; r++)
        s[ty + r * 8][tx] = W[(size_t)(k0 + ty + r * 8) * N + n0 + tx];
    __syncthreads();
#pragma unroll
    for (int r = 0; r < 4; r++) {
        int n = n0 + ty + r * 8;
        float a = s[tx][ty + r * 8];
        __nv_bfloat16 h = __float2bfloat16(a);
        __nv_bfloat16 l = __float2bfloat16(a - __bfloat162float(h));
        th[(size_t)(roff + n) * D_MODEL + k0 + tx] = h;
        tl[(size_t)(roff + n) * D_MODEL + k0 + tx] = l;
    }
}

// ---------------- HMMA bf16x3 GEMM: C[M,N] = A @ B^T ------------------------
#define GOP_B 8192
#define GBUF_B (4 * GOP_B)
#define GEMM_SMEM (3 * GBUF_B)  // 96KB

#define GSW(row, g) (((row) << 6) + ((((g) ^ (((row) >> 1) & 3)) << 4)))

__global__ void __launch_bounds__(256, 2)
gemm_hmma(const __nv_bfloat16* __restrict__ Ah, const __nv_bfloat16* __restrict__ Al,
          const __nv_bfloat16* __restrict__ Bh, const __nv_bfloat16* __restrict__ Bl,
          float* __restrict__ C, int K, int ldc) {
    extern __shared__ __align__(128) char gsm[];
    const int tid = threadIdx.x;
    const int lane = tid & 31;
    const int wid = tid >> 5;
    const int wm = (wid & 1) * 64;
    const int wn = (wid >> 1) * 32;
    const int bm = blockIdx.y * 128;
    const int bn = blockIdx.x * 128;
    const uint32_t sbase = smem_u32(gsm);

    const __nv_bfloat16* gptr[4] = {
        Ah + (size_t)bm * K, Al + (size_t)bm * K,
        Bh + (size_t)bn * K, Bl + (size_t)bn * K };

    // hoisted per-thread staging addresses (chunk-invariant)
    const __nv_bfloat16* srcb[8];
    uint32_t dstoff[8];
#pragma unroll
    for (int it = 0; it < 8; it++) {
        int s = it * 256 + tid;
        int op = s >> 9, t = s & 511;
        int row = t >> 2, cc = t & 3;
        srcb[it] = gptr[op] + (size_t)row * K + cc * 8;
        dstoff[it] = op * GOP_B + GSW(row, cc);
    }

    float acc[4][4][4];
#pragma unroll
    for (int a = 0; a < 4; a++)
#pragma unroll
        for (int b = 0; b < 4; b++)
#pragma unroll
            for (int c = 0; c < 4; c++) acc[a][b][c] = 0.f;

    const int a_row_l = lane & 15;
    const int a_gs = lane >> 4;
    const int b_row_l = ((lane & 16) ? 8 : 0) + (lane & 7);
    const int b_gs = (lane >> 3) & 1;

    const int nch = K >> 5;

    auto stage = [&](int c) {
        const int k0 = c << 5;
        const uint32_t dbase = sbase + (uint32_t)(c % 3) * GBUF_B;
#pragma unroll
        for (int it = 0; it < 8; it++)
            CPA16(dbase + dstoff[it], srcb[it] + k0);
        CPA_COMMIT;
    };

    stage(0);
    if (nch > 1) stage(1);

    for (int c = 0; c < nch; c++) {
        if (c + 1 < nch) { CPA_WAIT1; } else { CPA_WAIT0; }
        __syncthreads();
        if (c + 2 < nch) stage(c + 2);

        const uint32_t dbase = sbase + (uint32_t)(c % 3) * GBUF_B;
#pragma unroll
        for (int ks = 0; ks < 2; ks++) {
            const int kb2 = ks * 2;
            uint32_t bhf[2][4], blf[2][4];
#pragma unroll
            for (int np = 0; np < 2; np++) {
                int rb = wn + np * 16 + b_row_l;
                uint32_t offb = GSW(rb, kb2 + b_gs);
                LDM4(bhf[np], dbase + 2 * GOP_B + offb);
                LDM4(blf[np], dbase + 3 * GOP_B + offb);
            }
#pragma unroll
            for (int mt = 0; mt < 4; mt++) {
                uint32_t ahf[4], alf[4];
                int ra = wm + mt * 16 + a_row_l;
                uint32_t offa = GSW(ra, kb2 + a_gs);
                LDM4(ahf, dbase + offa);
                LDM4(alf, dbase + GOP_B + offa);
#pragma unroll
                for (int nt = 0; nt < 4; nt++) {
                    const int np = nt >> 1, sel = (nt & 1) * 2;
                    MMA16816(acc[mt][nt], ahf, bhf[np][sel], bhf[np][sel + 1]);
                    MMA16816(acc[mt][nt], ahf, blf[np][sel], blf[np][sel + 1]);
                    MMA16816(acc[mt][nt], alf, bhf[np][sel], bhf[np][sel + 1]);
                }
            }
        }
    }

#pragma unroll
    for (int mt = 0; mt < 4; mt++) {
        int r0 = bm + wm + mt * 16 + (lane >> 2);
#pragma unroll
        for (int nt = 0; nt < 4; nt++) {
            int c0 = bn + wn + nt * 8 + (lane & 3) * 2;
            *(float2*)(C + (size_t)r0 * ldc + c0) =
                make_float2(acc[mt][nt][0], acc[mt][nt][1]);
            *(float2*)(C + (size_t)(r0 + 8) * ldc + c0) =
                make_float2(acc[mt][nt][2], acc[mt][nt][3]);
        }
    }
}

// ---------------- fused RMS norm (+scale, +RoPE) -> split bf16 head-major --
// inv timescale via exp2f; trig via Cody-Waite reduction + MUFU sin/cos.
#define LOG2_BASE 13.287712379549449f
#define INV_2PI   0.15915494309189535f
#define C1_2PI    6.2831855f          // fp32(2*pi)
#define C2_2PI   -1.7484555e-7f       // 2*pi - C1_2PI

__global__ void norm_split_all(const float* __restrict__ qkv,
                               const float* __restrict__ q_scale,
                               const float* __restrict__ k_scale,
                               const int* __restrict__ positions,
                               __nv_bfloat16* __restrict__ qh, __nv_bfloat16* __restrict__ ql,
                               __nv_bfloat16* __restrict__ kh, __nv_bfloat16* __restrict__ kl,
                               __nv_bfloat16* __restrict__ vh, __nv_bfloat16* __restrict__ vl) {
    const int l = blockIdx.x;
    const int slot = blockIdx.y;   // 0..11
    int headoff, hh, do_rope;
    const float* scale;
    __nv_bfloat16 *oh, *ol;
    if (slot < 8)       { headoff = 0;    hh = slot;      scale = q_scale; do_rope = 1; oh = qh; ol = ql; }
    else if (slot < 10) { headoff = 2048; hh = slot - 8;  scale = k_scale; do_rope = 1; oh = kh; ol = kl; }
    else                { headoff = 2560; hh = slot - 10; scale = nullptr; do_rope = 0; oh = vh; ol = vl; }

    const float* p = qkv + (size_t)l * NQKV + headoff + hh * HD;
    const int t = threadIdx.x;  // 0..127
    const int lane = t & 31;
    const int wid = t >> 5;

    float a = p[t];
    float b = p[t + 128];
    float ss = a * a + b * b;
#pragma unroll
    for (int off = 16; off > 0; off >>= 1)
        ss += __shfl_xor_sync(0xffffffffu, ss, off);
    __shared__ float red4[4];
    if (lane == 0) red4[wid] = ss;
    __syncthreads();
    float total = red4[0] + red4[1] + red4[2] + red4[3];
    float inv = rsqrtf(total * (1.0f / HD) + 1e-6f);

    float xa = a * inv, xb = b * inv;
    if (scale) { xa *= scale[t]; xb *= scale[t + 128]; }

    float ya, yb;
    if (do_rope) {
        float pos = (float)positions[l];
        // inv_ts = 10000^(-2t/HD); ang = pos * inv_ts  (no divide)
        float inv_ts = exp2f(-(2.0f * (float)t / (float)HD) * LOG2_BASE);
        float ang = pos * inv_ts;
        // Cody-Waite range reduction to [-pi, pi]
        float n = rintf(ang * INV_2PI);
        float r = fmaf(-n, C1_2PI, ang);
        r = fmaf(-n, C2_2PI, r);
        float sn = __sinf(r);
        float cs = __cosf(r);
        ya = xa * cs - xb * sn;
        yb = xb * cs + xa * sn;
    } else {
        ya = xa; yb = xb;
    }
    size_t o = ((size_t)hh * L_SEQ + l) * HD;
    __nv_bfloat16 ha = __float2bfloat16(ya);
    __nv_bfloat16 hb = __float2bfloat16(yb);
    oh[o + t]       = ha;
    oh[o + t + 128] = hb;
    ol[o + t]       = __float2bfloat16(ya - __bfloat162float(ha));
    ol[o + t + 128] = __float2bfloat16(yb - __bfloat162float(hb));
}

// ---------------- tensor-core sliding-window flash attention ---------------
// Pipelined K (double-buffer) / V (single) staging; 112KB smem, 2 CTAs/SM.
#define QB 64
#define KT 16
#define ATT_SMEM (112 * 1024)

__global__ void __launch_bounds__(256, 2)
attn_tc(const __nv_bfloat16* __restrict__ qhp, const __nv_bfloat16* __restrict__ qlp,
        const __nv_bfloat16* __restrict__ khp, const __nv_bfloat16* __restrict__ klp,
        const __nv_bfloat16* __restrict__ vhp, const __nv_bfloat16* __restrict__ vlp,
        __nv_bfloat16* __restrict__ oh, __nv_bfloat16* __restrict__ ol) {
    extern __shared__ __align__(128) char asmem[];
    const int tid = threadIdx.x, lane = tid & 31, wid = tid >> 5;
    const int qb = blockIdx.x, h = blockIdx.y;
    const int kvh = h / (NH / NKVH);
    const int Q0 = qb * QB;
    const int qg = wid >> 1;
    const int dh = wid & 1;
    const uint32_t sb = smem_u32(asmem);
    const uint32_t sQ = sb;                     // hi; lo at +32768
    const uint32_t sK = sb + 65536;             // buf b at + b*16384 (Kh | Kl+8192)
    const uint32_t sV = sb + 98304;             // Vh | Vl+8192

    const __nv_bfloat16* kbh = khp + (size_t)kvh * L_SEQ * HD;
    const __nv_bfloat16* kbl = klp + (size_t)kvh * L_SEQ * HD;
    const __nv_bfloat16* vbh = vhp + (size_t)kvh * L_SEQ * HD;
    const __nv_bfloat16* vbl = vlp + (size_t)kvh * L_SEQ * HD;

    auto stage_tile = [&](const __nv_bfloat16* mh, const __nv_bfloat16* ml,
                          int kt, uint32_t dbase) {
#pragma unroll
        for (int r = 0; r < 4; r++) {
            int gid = r * 256 + tid;
            int mat = gid >> 9;
            int t = gid & 511;
            int row = t >> 5, g = t & 31;
            const __nv_bfloat16* src = (mat ? ml : mh) + (size_t)(kt + row) * HD + g * 8;
            uint32_t dst = dbase + mat * 8192 + row * 512 + ((g ^ (row & 7)) << 4);
            CPA16(dst, src);
        }
        CPA_COMMIT;
    };

    // ---- stage Q, then K0, then V0 (three groups)
#pragma unroll
    for (int i = 0; i < 16; i++) {
        int gid = i * 256 + tid;
        int mat = gid >> 11;
        int t = gid & 2047;
        int row = t >> 5, g = t & 31;
        const __nv_bfloat16* src = (mat ? qlp : qhp)
            + ((size_t)h * L_SEQ + Q0 + row) * HD + g * 8;
        uint32_t dst = sQ + mat * 32768 + row * 512 + ((g ^ (row & 7)) << 4);
        CPA16(dst, src);
    }
    CPA_COMMIT;

    int kstart = Q0 - (WINDOW - 1);
    if (kstart < 0) kstart = 0;
    kstart &= ~(KT - 1);
    const int kend = Q0 + QB;
    const int R0 = Q0 + qg * 16;

    stage_tile(kbh, kbl, kstart, sK);       // K0 -> buf 0
    stage_tile(vbh, vbl, kstart, sV);       // V0
    CPA_WAIT0;
    __syncthreads();

    float m0 = -1e9f, m1 = -1e9f;
    float l0 = 0.f, l1 = 0.f;
    float O[16][4];
#pragma unroll
    for (int nt = 0; nt < 16; nt++)
#pragma unroll
        for (int e = 0; e < 4; e++) O[nt][e] = 0.f;

    const int qa_r = ((lane >> 3) & 1) * 8 + (lane & 7);
    const int qa_gs = (lane >> 4);
    const int kb_r = ((lane >> 4) & 1) * 8 + (lane & 7);
    const int kb_gs = ((lane >> 3) & 1);
    const int vb_r = ((lane >> 3) & 1) * 8 + (lane & 7);
    const int vb_gs = (lane >> 4);

    int buf = 0;
    for (int kt = kstart; kt < kend; kt += KT, buf ^= 1) {
        const bool has_next = (kt + KT < kend);
        const uint32_t kB = sK + buf * 16384;

        float S[2][4];
#pragma unroll
        for (int nt = 0; nt < 2; nt++)
#pragma unroll
            for (int e = 0; e < 4; e++) S[nt][e] = 0.f;

#pragma unroll
        for (int ks = 0; ks < 16; ks++) {
            uint32_t qa[4], qal[4], kf[4], kfl[4];
            int qrow = qg * 16 + qa_r;
            int qg_g = ks * 2 + qa_gs;
            uint32_t qaddr = sQ + qrow * 512 + (((qg_g) ^ (qrow & 7)) << 4);
            LDM4(qa, qaddr);
            LDM4(qal, qaddr + 32768);
            int kg_g = ks * 2 + kb_gs;
            uint32_t kaddr = kB + kb_r * 512 + (((kg_g) ^ (kb_r & 7)) << 4);
            LDM4(kf, kaddr);
            LDM4(kfl, kaddr + 8192);
            MMA16816(S[0], qa, kf[0], kf[1]);
            MMA16816(S[0], qa, kfl[0], kfl[1]);
            MMA16816(S[0], qal, kf[0], kf[1]);
            MMA16816(S[1], qa, kf[2], kf[3]);
            MMA16816(S[1], qa, kfl[2], kfl[3]);
            MMA16816(S[1], qal, kf[2], kf[3]);
        }

        if (has_next) stage_tile(kbh, kbl, kt + KT, sK + (buf ^ 1) * 16384);

        if (has_next) { CPA_WAIT1; } else { CPA_WAIT0; }
        __syncthreads();

        const bool fullvalid = (kt + KT - 1 <= R0) && (kt >= R0 + 15 - (WINDOW - 1));
        if (!fullvalid) {
            int rq0 = R0 + (lane >> 2);
            int ck = kt + (lane & 3) * 2;
#pragma unroll
            for (int nt = 0; nt < 2; nt++)
#pragma unroll
                for (int e = 0; e < 4; e++) {
                    int q = rq0 + ((e >= 2) ? 8 : 0);
                    int k = ck + nt * 8 + (e & 1);
                    if (k > q || k < q - (WINDOW - 1)) S[nt][e] = -1e30f;
                }
        }

        float tm0 = fmaxf(fmaxf(S[0][0], S[0][1]), fmaxf(S[1][0], S[1][1]));
        float tm1 = fmaxf(fmaxf(S[0][2], S[0][3]), fmaxf(S[1][2], S[1][3]));
        tm0 = fmaxf(tm0, __shfl_xor_sync(0xffffffffu, tm0, 1));
        tm0 = fmaxf(tm0, __shfl_xor_sync(0xffffffffu, tm0, 2));
        tm1 = fmaxf(tm1, __shfl_xor_sync(0xffffffffu, tm1, 1));
        tm1 = fmaxf(tm1, __shfl_xor_sync(0xffffffffu, tm1, 2));
        float mn0 = fmaxf(m0, tm0), mn1 = fmaxf(m1, tm1);
        float sc0 = __expf(m0 - mn0), sc1 = __expf(m1 - mn1);
        m0 = mn0; m1 = mn1;

        float p[2][4];
#pragma unroll
        for (int nt = 0; nt < 2; nt++) {
            p[nt][0] = __expf(S[nt][0] - mn0);
            p[nt][1] = __expf(S[nt][1] - mn0);
            p[nt][2] = __expf(S[nt][2] - mn1);
            p[nt][3] = __expf(S[nt][3] - mn1);
        }
        float rs0 = p[0][0] + p[0][1] + p[1][0] + p[1][1];
        float rs1 = p[0][2] + p[0][3] + p[1][2] + p[1][3];
        rs0 += __shfl_xor_sync(0xffffffffu, rs0, 1);
        rs0 += __shfl_xor_sync(0xffffffffu, rs0, 2);
        rs1 += __shfl_xor_sync(0xffffffffu, rs1, 1);
        rs1 += __shfl_xor_sync(0xffffffffu, rs1, 2);
        l0 = l0 * sc0 + rs0;
        l1 = l1 * sc1 + rs1;

#pragma unroll
        for (int nt = 0; nt < 16; nt++) {
            O[nt][0] *= sc0; O[nt][1] *= sc0;
            O[nt][2] *= sc1; O[nt][3] *= sc1;
        }

        uint32_t pa[4], pal[4];
#pragma unroll
        for (int e = 0; e < 4; e++) {
            int nt = e >> 1, half = (e & 1) * 2;
            float v0 = p[nt][half], v1 = p[nt][half + 1];
            __nv_bfloat16 h0 = __float2bfloat16(v0);
            __nv_bfloat16 h1 = __float2bfloat16(v1);
            __nv_bfloat162 hh2{h0, h1};
            __nv_bfloat162 ll2{__float2bfloat16(v0 - __bfloat162float(h0)),
                               __float2bfloat16(v1 - __bfloat162float(h1))};
            pa[e] = *(uint32_t*)&hh2;
            pal[e] = *(uint32_t*)&ll2;
        }

#pragma unroll
        for (int j = 0; j < 8; j++) {
            uint32_t vf[4], vfl[4];
            int vg = dh * 16 + j * 2 + vb_gs;
            uint32_t vaddr = sV + vb_r * 512 + (((vg) ^ (vb_r & 7)) << 4);
            LDM4T(vf, vaddr);
            LDM4T(vfl, vaddr + 8192);
            MMA16816(O[2 * j], pa, vf[0], vf[1]);
            MMA16816(O[2 * j], pa, vfl[0], vfl[1]);
            MMA16816(O[2 * j], pal, vf[0], vf[1]);
            MMA16816(O[2 * j + 1], pa, vf[2], vf[3]);
            MMA16816(O[2 * j + 1], pa, vfl[2], vfl[3]);
            MMA16816(O[2 * j + 1], pal, vf[2], vf[3]);
        }

        if (has_next) {
            __syncthreads();                       // PV readers done; V buffer free
            stage_tile(vbh, vbl, kt + KT, sV);     // pending: [K_{i+1}, V_{i+1}]
            CPA_WAIT1;                             // K_{i+1} done
            __syncthreads();                       // K_{i+1} visible to all
        }
    }

    float il0 = 1.0f / l0, il1 = 1.0f / l1;
    int row0 = Q0 + qg * 16 + (lane >> 2);
#pragma unroll
    for (int nt = 0; nt < 16; nt++) {
        int n = dh * 128 + nt * 8 + (lane & 3) * 2;
        size_t base0 = (size_t)row0 * D_MODEL + h * HD + n;
        size_t base1 = (size_t)(row0 + 8) * D_MODEL + h * HD + n;
        float v0 = O[nt][0] * il0, v1 = O[nt][1] * il0;
        float v2 = O[nt][2] * il1, v3 = O[nt][3] * il1;
        __nv_bfloat16 h0 = __float2bfloat16(v0), h1 = __float2bfloat16(v1);
        __nv_bfloat16 h2 = __float2bfloat16(v2), h3 = __float2bfloat16(v3);
        *(__nv_bfloat162*)(oh + base0) = __nv_bfloat162{h0, h1};
        *(__nv_bfloat162*)(oh + base1) = __nv_bfloat162{h2, h3};
        *(__nv_bfloat162*)(ol + base0) =
            __nv_bfloat162{__float2bfloat16(v0 - __bfloat162float(h0)),
                           __float2bfloat16(v1 - __bfloat162float(h1))};
        *(__nv_bfloat162*)(ol + base1) =
            __nv_bfloat162{__float2bfloat16(v2 - __bfloat162float(h2)),
                           __float2bfloat16(v3 - __bfloat162float(h3))};
    }
}

// ---------------------------------------------------------------------------
extern "C" void kernel_launch(void* const* d_in, const int* in_sizes, int n_in,
                              void* d_out, int out_size) {
    const float* x       = (const float*)d_in[0];
    const int* positions = (const int*)d_in[1];
    const float* Wq      = (const float*)d_in[2];
    const float* Wk      = (const float*)d_in[3];
    const float* Wv      = (const float*)d_in[4];
    const float* Wo      = (const float*)d_in[5];
    const float* q_scale = (const float*)d_in[6];
    const float* k_scale = (const float*)d_in[7];
    float* out           = (float*)d_out;

    __nv_bfloat16 *ah, *al, *wqh, *wql, *woh, *wol, *qh, *ql, *kh, *kl, *vh, *vl;
    float* qkv;
    cudaGetSymbolAddress((void**)&ah, g_ah);
    cudaGetSymbolAddress((void**)&al, g_al);
    cudaGetSymbolAddress((void**)&wqh, g_wqkv_h);
    cudaGetSymbolAddress((void**)&wql, g_wqkv_l);
    cudaGetSymbolAddress((void**)&woh, g_wo_h);
    cudaGetSymbolAddress((void**)&wol, g_wo_l);
    cudaGetSymbolAddress((void**)&qh, g_qh);
    cudaGetSymbolAddress((void**)&ql, g_ql);
    cudaGetSymbolAddress((void**)&kh, g_kh);
    cudaGetSymbolAddress((void**)&kl, g_kl);
    cudaGetSymbolAddress((void**)&vh, g_vh);
    cudaGetSymbolAddress((void**)&vl, g_vl);
    cudaGetSymbolAddress((void**)&qkv, g_qkv);

    cudaFuncSetAttribute(gemm_hmma, cudaFuncAttributeMaxDynamicSharedMemorySize,
                         GEMM_SMEM);
    cudaFuncSetAttribute(attn_tc, cudaFuncAttributeMaxDynamicSharedMemorySize,
                         ATT_SMEM);

    // fused weight transpose+split (one launch)
    tsplit_all<<<dim3(160, 64), dim3(32, 8)>>>(Wq, Wk, Wv, Wo, wqh, wql, woh, wol);

    // activations: bf16 split
    int n4 = (L_SEQ * D_MODEL) / 4;
    split_kernel<<<(n4 + 255) / 256, 256>>>(x, ah, al, n4);

    // fused QKV projection
    gemm_hmma<<<dim3(NQKV / 128, L_SEQ / 128), 256, GEMM_SMEM>>>(
        ah, al, wqh, wql, qkv, D_MODEL, NQKV);

    // fused norm (+rope) + split
    norm_split_all<<<dim3(L_SEQ, 12), 128>>>(qkv, q_scale, k_scale, positions,
                                             qh, ql, kh, kl, vh, vl);

    // pipelined tensor-core attention; writes split O into ah/al
    attn_tc<<<dim3(L_SEQ / QB, NH), 256, ATT_SMEM>>>(qh, ql, kh, kl, vh, vl, ah, al);

    // output projection
    gemm_hmma<<<dim3(D_MODEL / 128, L_SEQ / 128), 256, GEMM_SMEM>>>(
        ah, al, woh, wol, out, D_MODEL, D_MODEL);
}

// round 15
// speedup vs baseline: 1.6438x; 1.0780x over previous
#include <cuda_runtime.h>
#include <cuda_bf16.h>
#include <cuda_fp16.h>
#include <math.h>
#include <stdint.h>

#define L_SEQ 4096
#define D_MODEL 2048
#define NH 8
#define NKVH 2
#define HD 256
#define WINDOW 512
#define NQKV 3072  // 2048 q + 512 k + 512 v

// ---------------- scratch (device globals; no cudaMalloc allowed) ----------
__device__ __nv_bfloat16 g_ah[L_SEQ * D_MODEL];        // x hi (bf16) then O hi (fp16)
__device__ __nv_bfloat16 g_al[L_SEQ * D_MODEL];        // x lo (bf16) then O lo (fp16)
__device__ __nv_bfloat16 g_wqkv_h[NQKV * D_MODEL];     // [Wq|Wk|Wv]^T hi, (N,K)
__device__ __nv_bfloat16 g_wqkv_l[NQKV * D_MODEL];
__device__ __nv_bfloat16 g_wo_h[D_MODEL * D_MODEL];    // Wo^T fp16 hi
__device__ __nv_bfloat16 g_wo_l[D_MODEL * D_MODEL];    // (unused lo, kept for layout)
__device__ float g_qkv[L_SEQ * NQKV];                  // fused qkv activations
// head-major split q/k/v for attention
__device__ __nv_bfloat16 g_qh[NH * L_SEQ * HD];
__device__ __nv_bfloat16 g_ql[NH * L_SEQ * HD];
__device__ __nv_bfloat16 g_kh[NKVH * L_SEQ * HD];
__device__ __nv_bfloat16 g_kl[NKVH * L_SEQ * HD];
__device__ __nv_bfloat16 g_vh[NKVH * L_SEQ * HD];
__device__ __nv_bfloat16 g_vl[NKVH * L_SEQ * HD];

static __device__ __forceinline__ uint32_t smem_u32(const void* p) {
    uint32_t a;
    asm("{ .reg .u64 t; cvta.to.shared.u64 t, %1; cvt.u32.u64 %0, t; }"
        : "=r"(a) : "l"(p));
    return a;
}

#define CPA16(dst, src)                                                        \
    asm volatile("cp.async.cg.shared.global [%0], [%1], 16;"                   \
                 :: "r"(dst), "l"(src) : "memory")
#define CPA_COMMIT asm volatile("cp.async.commit_group;" ::: "memory")
#define CPA_WAIT0  asm volatile("cp.async.wait_group 0;" ::: "memory")
#define CPA_WAIT1  asm volatile("cp.async.wait_group 1;" ::: "memory")

#define LDM4(r, addr)                                                          \
    asm volatile("ldmatrix.sync.aligned.m8n8.x4.shared.b16 {%0,%1,%2,%3}, [%4];"\
        : "=r"((r)[0]), "=r"((r)[1]), "=r"((r)[2]), "=r"((r)[3]) : "r"(addr))

#define LDM4T(r, addr)                                                         \
    asm volatile("ldmatrix.sync.aligned.m8n8.x4.trans.shared.b16 {%0,%1,%2,%3}, [%4];"\
        : "=r"((r)[0]), "=r"((r)[1]), "=r"((r)[2]), "=r"((r)[3]) : "r"(addr))

#define MMA16816(c, a, b0v, b1v)                                               \
    asm volatile("mma.sync.aligned.m16n8k16.row.col.f32.bf16.bf16.f32 "        \
        "{%0,%1,%2,%3}, {%4,%5,%6,%7}, {%8,%9}, {%0,%1,%2,%3};"                \
        : "+f"((c)[0]), "+f"((c)[1]), "+f"((c)[2]), "+f"((c)[3])               \
        : "r"((a)[0]), "r"((a)[1]), "r"((a)[2]), "r"((a)[3]),                  \
          "r"(b0v), "r"(b1v))

#define MMA16816F(c, a, b0v, b1v)                                              \
    asm volatile("mma.sync.aligned.m16n8k16.row.col.f32.f16.f16.f32 "          \
        "{%0,%1,%2,%3}, {%4,%5,%6,%7}, {%8,%9}, {%0,%1,%2,%3};"                \
        : "+f"((c)[0]), "+f"((c)[1]), "+f"((c)[2]), "+f"((c)[3])               \
        : "r"((a)[0]), "r"((a)[1]), "r"((a)[2]), "r"((a)[3]),                  \
          "r"(b0v), "r"(b1v))

// ---------------- split fp32 -> bf16 hi/lo (vector x4) ---------------------
__global__ void split_kernel(const float* __restrict__ in,
                             __nv_bfloat16* __restrict__ hi,
                             __nv_bfloat16* __restrict__ lo, int n4) {
    int i = blockIdx.x * blockDim.x + threadIdx.x;
    if (i >= n4) return;
    float4 a = ((const float4*)in)[i];
    __nv_bfloat16 h0 = __float2bfloat16(a.x);
    __nv_bfloat16 h1 = __float2bfloat16(a.y);
    __nv_bfloat16 h2 = __float2bfloat16(a.z);
    __nv_bfloat16 h3 = __float2bfloat16(a.w);
    __nv_bfloat16 l0 = __float2bfloat16(a.x - __bfloat162float(h0));
    __nv_bfloat16 l1 = __float2bfloat16(a.y - __bfloat162float(h1));
    __nv_bfloat16 l2 = __float2bfloat16(a.z - __bfloat162float(h2));
    __nv_bfloat16 l3 = __float2bfloat16(a.w - __bfloat162float(h3));
    __nv_bfloat162* ph = (__nv_bfloat162*)hi;
    __nv_bfloat162* pl = (__nv_bfloat162*)lo;
    ph[i * 2]     = __nv_bfloat162{h0, h1};
    ph[i * 2 + 1] = __nv_bfloat162{h2, h3};
    pl[i * 2]     = __nv_bfloat162{l0, l1};
    pl[i * 2 + 1] = __nv_bfloat162{l2, l3};
}

// ---------------- fused transpose+split of all weights ---------------------
// [0,64) Wq | [64,80) Wk | [80,96) Wv  -> bf16 hi/lo into wq buffers
// [96,160) Wo -> fp16 hi into woh (lo written but unused)
__global__ void tsplit_all(const float* __restrict__ Wq, const float* __restrict__ Wk,
                           const float* __restrict__ Wv, const float* __restrict__ Wo,
                           __nv_bfloat16* __restrict__ wqh, __nv_bfloat16* __restrict__ wql,
                           __nv_bfloat16* __restrict__ woh, __nv_bfloat16* __restrict__ wol) {
    __shared__ float s[32][33];
    int bx = blockIdx.x;
    const float* W; __nv_bfloat16 *th, *tl; int N, roff, f16 = 0;
    if (bx < 64)      { W = Wq; N = 2048; roff = 0;    th = wqh; tl = wql; }
    else if (bx < 80) { W = Wk; N = 512;  roff = 2048; th = wqh; tl = wql; bx -= 64; }
    else if (bx < 96) { W = Wv; N = 512;  roff = 2560; th = wqh; tl = wql; bx -= 80; }
    else              { W = Wo; N = 2048; roff = 0;    th = woh; tl = wol; bx -= 96; f16 = 1; }

    int n0 = bx * 32, k0 = blockIdx.y * 32;
    int tx = threadIdx.x, ty = threadIdx.y;  // 32 x 8
#pragma unroll
    for (int r = 0; r < 4; r++)
        s[ty + r * 8][tx] = W[(size_t)(k0 + ty + r * 8) * N + n0 + tx];
    __syncthreads();
#pragma unroll
    for (int r = 0; r < 4; r++) {
        int n = n0 + ty + r * 8;
        float a = s[tx][ty + r * 8];
        size_t off = (size_t)(roff + n) * D_MODEL + k0 + tx;
        if (f16) {
            __half h = __float2half(a);
            ((__half*)th)[off] = h;
            ((__half*)tl)[off] = __float2half(a - __half2float(h));
        } else {
            __nv_bfloat16 h = __float2bfloat16(a);
            th[off] = h;
            tl[off] = __float2bfloat16(a - __bfloat162float(h));
        }
    }
}

// ---------------- HMMA bf16x3 GEMM: C[M,N] = A @ B^T ------------------------
#define GOP_B 8192
#define GBUF_B (4 * GOP_B)
#define GEMM_SMEM (3 * GBUF_B)  // 96KB

#define GSW(row, g) (((row) << 6) + ((((g) ^ (((row) >> 1) & 3)) << 4)))

__global__ void __launch_bounds__(256, 2)
gemm_hmma(const __nv_bfloat16* __restrict__ Ah, const __nv_bfloat16* __restrict__ Al,
          const __nv_bfloat16* __restrict__ Bh, const __nv_bfloat16* __restrict__ Bl,
          float* __restrict__ C, int K, int ldc) {
    extern __shared__ __align__(128) char gsm[];
    const int tid = threadIdx.x;
    const int lane = tid & 31;
    const int wid = tid >> 5;
    const int wm = (wid & 1) * 64;
    const int wn = (wid >> 1) * 32;
    const int bm = blockIdx.y * 128;
    const int bn = blockIdx.x * 128;
    const uint32_t sbase = smem_u32(gsm);

    const __nv_bfloat16* gptr[4] = {
        Ah + (size_t)bm * K, Al + (size_t)bm * K,
        Bh + (size_t)bn * K, Bl + (size_t)bn * K };

    const __nv_bfloat16* srcb[8];
    uint32_t dstoff[8];
#pragma unroll
    for (int it = 0; it < 8; it++) {
        int s = it * 256 + tid;
        int op = s >> 9, t = s & 511;
        int row = t >> 2, cc = t & 3;
        srcb[it] = gptr[op] + (size_t)row * K + cc * 8;
        dstoff[it] = op * GOP_B + GSW(row, cc);
    }

    float acc[4][4][4];
#pragma unroll
    for (int a = 0; a < 4; a++)
#pragma unroll
        for (int b = 0; b < 4; b++)
#pragma unroll
            for (int c = 0; c < 4; c++) acc[a][b][c] = 0.f;

    const int a_row_l = lane & 15;
    const int a_gs = lane >> 4;
    const int b_row_l = ((lane & 16) ? 8 : 0) + (lane & 7);
    const int b_gs = (lane >> 3) & 1;

    const int nch = K >> 5;

    auto stage = [&](int c) {
        const int k0 = c << 5;
        const uint32_t dbase = sbase + (uint32_t)(c % 3) * GBUF_B;
#pragma unroll
        for (int it = 0; it < 8; it++)
            CPA16(dbase + dstoff[it], srcb[it] + k0);
        CPA_COMMIT;
    };

    stage(0);
    if (nch > 1) stage(1);

    for (int c = 0; c < nch; c++) {
        if (c + 1 < nch) { CPA_WAIT1; } else { CPA_WAIT0; }
        __syncthreads();
        if (c + 2 < nch) stage(c + 2);

        const uint32_t dbase = sbase + (uint32_t)(c % 3) * GBUF_B;
#pragma unroll
        for (int ks = 0; ks < 2; ks++) {
            const int kb2 = ks * 2;
            uint32_t bhf[2][4], blf[2][4];
#pragma unroll
            for (int np = 0; np < 2; np++) {
                int rb = wn + np * 16 + b_row_l;
                uint32_t offb = GSW(rb, kb2 + b_gs);
                LDM4(bhf[np], dbase + 2 * GOP_B + offb);
                LDM4(blf[np], dbase + 3 * GOP_B + offb);
            }
#pragma unroll
            for (int mt = 0; mt < 4; mt++) {
                uint32_t ahf[4], alf[4];
                int ra = wm + mt * 16 + a_row_l;
                uint32_t offa = GSW(ra, kb2 + a_gs);
                LDM4(ahf, dbase + offa);
                LDM4(alf, dbase + GOP_B + offa);
#pragma unroll
                for (int nt = 0; nt < 4; nt++) {
                    const int np = nt >> 1, sel = (nt & 1) * 2;
                    MMA16816(acc[mt][nt], ahf, bhf[np][sel], bhf[np][sel + 1]);
                    MMA16816(acc[mt][nt], ahf, blf[np][sel], blf[np][sel + 1]);
                    MMA16816(acc[mt][nt], alf, bhf[np][sel], bhf[np][sel + 1]);
                }
            }
        }
    }

#pragma unroll
    for (int mt = 0; mt < 4; mt++) {
        int r0 = bm + wm + mt * 16 + (lane >> 2);
#pragma unroll
        for (int nt = 0; nt < 4; nt++) {
            int c0 = bn + wn + nt * 8 + (lane & 3) * 2;
            *(float2*)(C + (size_t)r0 * ldc + c0) =
                make_float2(acc[mt][nt][0], acc[mt][nt][1]);
            *(float2*)(C + (size_t)(r0 + 8) * ldc + c0) =
                make_float2(acc[mt][nt][2], acc[mt][nt][3]);
        }
    }
}

// ---------------- HMMA fp16 2-term GEMM: C = A @ B^T ------------------------
// A fp16 hi/lo; B fp16 hi only. acc = ah*bh + al*bh. 3 operands, 2 MMAs/step.
#define FBUF_B (3 * GOP_B)        // 24KB per stage
#define GEMM_F16_SMEM (3 * FBUF_B)  // 72KB

__global__ void __launch_bounds__(256, 2)
gemm_f16(const __half* __restrict__ Ah, const __half* __restrict__ Al,
         const __half* __restrict__ Bh, float* __restrict__ C, int K, int ldc) {
    extern __shared__ __align__(128) char gsm[];
    const int tid = threadIdx.x;
    const int lane = tid & 31;
    const int wid = tid >> 5;
    const int wm = (wid & 1) * 64;
    const int wn = (wid >> 1) * 32;
    const int bm = blockIdx.y * 128;
    const int bn = blockIdx.x * 128;
    const uint32_t sbase = smem_u32(gsm);

    const __half* gptr[3] = {
        Ah + (size_t)bm * K, Al + (size_t)bm * K, Bh + (size_t)bn * K };

    const __half* srcb[6];
    uint32_t dstoff[6];
#pragma unroll
    for (int it = 0; it < 6; it++) {
        int s = it * 256 + tid;
        int op = s >> 9, t = s & 511;
        int row = t >> 2, cc = t & 3;
        srcb[it] = gptr[op] + (size_t)row * K + cc * 8;
        dstoff[it] = op * GOP_B + GSW(row, cc);
    }

    float acc[4][4][4];
#pragma unroll
    for (int a = 0; a < 4; a++)
#pragma unroll
        for (int b = 0; b < 4; b++)
#pragma unroll
            for (int c = 0; c < 4; c++) acc[a][b][c] = 0.f;

    const int a_row_l = lane & 15;
    const int a_gs = lane >> 4;
    const int b_row_l = ((lane & 16) ? 8 : 0) + (lane & 7);
    const int b_gs = (lane >> 3) & 1;

    const int nch = K >> 5;

    auto stage = [&](int c) {
        const int k0 = c << 5;
        const uint32_t dbase = sbase + (uint32_t)(c % 3) * FBUF_B;
#pragma unroll
        for (int it = 0; it < 6; it++)
            CPA16(dbase + dstoff[it], srcb[it] + k0);
        CPA_COMMIT;
    };

    stage(0);
    if (nch > 1) stage(1);

    for (int c = 0; c < nch; c++) {
        if (c + 1 < nch) { CPA_WAIT1; } else { CPA_WAIT0; }
        __syncthreads();
        if (c + 2 < nch) stage(c + 2);

        const uint32_t dbase = sbase + (uint32_t)(c % 3) * FBUF_B;
#pragma unroll
        for (int ks = 0; ks < 2; ks++) {
            const int kb2 = ks * 2;
            uint32_t bhf[2][4];
#pragma unroll
            for (int np = 0; np < 2; np++) {
                int rb = wn + np * 16 + b_row_l;
                uint32_t offb = GSW(rb, kb2 + b_gs);
                LDM4(bhf[np], dbase + 2 * GOP_B + offb);
            }
#pragma unroll
            for (int mt = 0; mt < 4; mt++) {
                uint32_t ahf[4], alf[4];
                int ra = wm + mt * 16 + a_row_l;
                uint32_t offa = GSW(ra, kb2 + a_gs);
                LDM4(ahf, dbase + offa);
                LDM4(alf, dbase + GOP_B + offa);
#pragma unroll
                for (int nt = 0; nt < 4; nt++) {
                    const int np = nt >> 1, sel = (nt & 1) * 2;
                    MMA16816F(acc[mt][nt], ahf, bhf[np][sel], bhf[np][sel + 1]);
                    MMA16816F(acc[mt][nt], alf, bhf[np][sel], bhf[np][sel + 1]);
                }
            }
        }
    }

#pragma unroll
    for (int mt = 0; mt < 4; mt++) {
        int r0 = bm + wm + mt * 16 + (lane >> 2);
#pragma unroll
        for (int nt = 0; nt < 4; nt++) {
            int c0 = bn + wn + nt * 8 + (lane & 3) * 2;
            *(float2*)(C + (size_t)r0 * ldc + c0) =
                make_float2(acc[mt][nt][0], acc[mt][nt][1]);
            *(float2*)(C + (size_t)(r0 + 8) * ldc + c0) =
                make_float2(acc[mt][nt][2], acc[mt][nt][3]);
        }
    }
}

// ---------------- fused RMS norm (+scale, +RoPE) -> split bf16 head-major --
#define LOG2_BASE 13.287712379549449f
#define INV_2PI   0.15915494309189535f
#define C1_2PI    6.2831855f
#define C2_2PI   -1.7484555e-7f

__global__ void norm_split_all(const float* __restrict__ qkv,
                               const float* __restrict__ q_scale,
                               const float* __restrict__ k_scale,
                               const int* __restrict__ positions,
                               __nv_bfloat16* __restrict__ qh, __nv_bfloat16* __restrict__ ql,
                               __nv_bfloat16* __restrict__ kh, __nv_bfloat16* __restrict__ kl,
                               __nv_bfloat16* __restrict__ vh, __nv_bfloat16* __restrict__ vl) {
    const int l = blockIdx.x;
    const int slot = blockIdx.y;   // 0..11
    int headoff, hh, do_rope;
    const float* scale;
    __nv_bfloat16 *oh, *ol;
    if (slot < 8)       { headoff = 0;    hh = slot;      scale = q_scale; do_rope = 1; oh = qh; ol = ql; }
    else if (slot < 10) { headoff = 2048; hh = slot - 8;  scale = k_scale; do_rope = 1; oh = kh; ol = kl; }
    else                { headoff = 2560; hh = slot - 10; scale = nullptr; do_rope = 0; oh = vh; ol = vl; }

    const float* p = qkv + (size_t)l * NQKV + headoff + hh * HD;
    const int t = threadIdx.x;  // 0..127
    const int lane = t & 31;
    const int wid = t >> 5;

    float a = p[t];
    float b = p[t + 128];
    float ss = a * a + b * b;
#pragma unroll
    for (int off = 16; off > 0; off >>= 1)
        ss += __shfl_xor_sync(0xffffffffu, ss, off);
    __shared__ float red4[4];
    if (lane == 0) red4[wid] = ss;
    __syncthreads();
    float total = red4[0] + red4[1] + red4[2] + red4[3];
    float inv = rsqrtf(total * (1.0f / HD) + 1e-6f);

    float xa = a * inv, xb = b * inv;
    if (scale) { xa *= scale[t]; xb *= scale[t + 128]; }

    float ya, yb;
    if (do_rope) {
        float pos = (float)positions[l];
        float inv_ts = exp2f(-(2.0f * (float)t / (float)HD) * LOG2_BASE);
        float ang = pos * inv_ts;
        float n = rintf(ang * INV_2PI);
        float r = fmaf(-n, C1_2PI, ang);
        r = fmaf(-n, C2_2PI, r);
        float sn = __sinf(r);
        float cs = __cosf(r);
        ya = xa * cs - xb * sn;
        yb = xb * cs + xa * sn;
    } else {
        ya = xa; yb = xb;
    }
    size_t o = ((size_t)hh * L_SEQ + l) * HD;
    __nv_bfloat16 ha = __float2bfloat16(ya);
    __nv_bfloat16 hb = __float2bfloat16(yb);
    oh[o + t]       = ha;
    oh[o + t + 128] = hb;
    ol[o + t]       = __float2bfloat16(ya - __bfloat162float(ha));
    ol[o + t + 128] = __float2bfloat16(yb - __bfloat162float(hb));
}

// ---------------- tensor-core sliding-window flash attention ---------------
// Pipelined K (double-buffer) / V (single) staging; 112KB smem, 2 CTAs/SM.
// Epilogue writes O split as fp16 (for the fp16 Wo GEMM).
#define QB 64
#define KT 16
#define ATT_SMEM (112 * 1024)

__global__ void __launch_bounds__(256, 2)
attn_tc(const __nv_bfloat16* __restrict__ qhp, const __nv_bfloat16* __restrict__ qlp,
        const __nv_bfloat16* __restrict__ khp, const __nv_bfloat16* __restrict__ klp,
        const __nv_bfloat16* __restrict__ vhp, const __nv_bfloat16* __restrict__ vlp,
        __half* __restrict__ oh, __half* __restrict__ ol) {
    extern __shared__ __align__(128) char asmem[];
    const int tid = threadIdx.x, lane = tid & 31, wid = tid >> 5;
    const int qb = blockIdx.x, h = blockIdx.y;
    const int kvh = h / (NH / NKVH);
    const int Q0 = qb * QB;
    const int qg = wid >> 1;
    const int dh = wid & 1;
    const uint32_t sb = smem_u32(asmem);
    const uint32_t sQ = sb;                     // hi; lo at +32768
    const uint32_t sK = sb + 65536;             // buf b at + b*16384 (Kh | Kl+8192)
    const uint32_t sV = sb + 98304;             // Vh | Vl+8192

    const __nv_bfloat16* kbh = khp + (size_t)kvh * L_SEQ * HD;
    const __nv_bfloat16* kbl = klp + (size_t)kvh * L_SEQ * HD;
    const __nv_bfloat16* vbh = vhp + (size_t)kvh * L_SEQ * HD;
    const __nv_bfloat16* vbl = vlp + (size_t)kvh * L_SEQ * HD;

    auto stage_tile = [&](const __nv_bfloat16* mh, const __nv_bfloat16* ml,
                          int kt, uint32_t dbase) {
#pragma unroll
        for (int r = 0; r < 4; r++) {
            int gid = r * 256 + tid;
            int mat = gid >> 9;
            int t = gid & 511;
            int row = t >> 5, g = t & 31;
            const __nv_bfloat16* src = (mat ? ml : mh) + (size_t)(kt + row) * HD + g * 8;
            uint32_t dst = dbase + mat * 8192 + row * 512 + ((g ^ (row & 7)) << 4);
            CPA16(dst, src);
        }
        CPA_COMMIT;
    };

    // ---- stage Q, then K0, then V0 (three groups)
#pragma unroll
    for (int i = 0; i < 16; i++) {
        int gid = i * 256 + tid;
        int mat = gid >> 11;
        int t = gid & 2047;
        int row = t >> 5, g = t & 31;
        const __nv_bfloat16* src = (mat ? qlp : qhp)
            + ((size_t)h * L_SEQ + Q0 + row) * HD + g * 8;
        uint32_t dst = sQ + mat * 32768 + row * 512 + ((g ^ (row & 7)) << 4);
        CPA16(dst, src);
    }
    CPA_COMMIT;

    int kstart = Q0 - (WINDOW - 1);
    if (kstart < 0) kstart = 0;
    kstart &= ~(KT - 1);
    const int kend = Q0 + QB;
    const int R0 = Q0 + qg * 16;

    stage_tile(kbh, kbl, kstart, sK);       // K0 -> buf 0
    stage_tile(vbh, vbl, kstart, sV);       // V0
    CPA_WAIT0;
    __syncthreads();

    float m0 = -1e9f, m1 = -1e9f;
    float l0 = 0.f, l1 = 0.f;
    float O[16][4];
#pragma unroll
    for (int nt = 0; nt < 16; nt++)
#pragma unroll
        for (int e = 0; e < 4; e++) O[nt][e] = 0.f;

    const int qa_r = ((lane >> 3) & 1) * 8 + (lane & 7);
    const int qa_gs = (lane >> 4);
    const int kb_r = ((lane >> 4) & 1) * 8 + (lane & 7);
    const int kb_gs = ((lane >> 3) & 1);
    const int vb_r = ((lane >> 3) & 1) * 8 + (lane & 7);
    const int vb_gs = (lane >> 4);

    int buf = 0;
    for (int kt = kstart; kt < kend; kt += KT, buf ^= 1) {
        const bool has_next = (kt + KT < kend);
        const uint32_t kB = sK + buf * 16384;

        float S[2][4];
#pragma unroll
        for (int nt = 0; nt < 2; nt++)
#pragma unroll
            for (int e = 0; e < 4; e++) S[nt][e] = 0.f;

#pragma unroll
        for (int ks = 0; ks < 16; ks++) {
            uint32_t qa[4], qal[4], kf[4], kfl[4];
            int qrow = qg * 16 + qa_r;
            int qg_g = ks * 2 + qa_gs;
            uint32_t qaddr = sQ + qrow * 512 + (((qg_g) ^ (qrow & 7)) << 4);
            LDM4(qa, qaddr);
            LDM4(qal, qaddr + 32768);
            int kg_g = ks * 2 + kb_gs;
            uint32_t kaddr = kB + kb_r * 512 + (((kg_g) ^ (kb_r & 7)) << 4);
            LDM4(kf, kaddr);
            LDM4(kfl, kaddr + 8192);
            MMA16816(S[0], qa, kf[0], kf[1]);
            MMA16816(S[0], qa, kfl[0], kfl[1]);
            MMA16816(S[0], qal, kf[0], kf[1]);
            MMA16816(S[1], qa, kf[2], kf[3]);
            MMA16816(S[1], qa, kfl[2], kfl[3]);
            MMA16816(S[1], qal, kf[2], kf[3]);
        }

        if (has_next) stage_tile(kbh, kbl, kt + KT, sK + (buf ^ 1) * 16384);

        if (has_next) { CPA_WAIT1; } else { CPA_WAIT0; }
        __syncthreads();

        const bool fullvalid = (kt + KT - 1 <= R0) && (kt >= R0 + 15 - (WINDOW - 1));
        if (!fullvalid) {
            int rq0 = R0 + (lane >> 2);
            int ck = kt + (lane & 3) * 2;
#pragma unroll
            for (int nt = 0; nt < 2; nt++)
#pragma unroll
                for (int e = 0; e < 4; e++) {
                    int q = rq0 + ((e >= 2) ? 8 : 0);
                    int k = ck + nt * 8 + (e & 1);
                    if (k > q || k < q - (WINDOW - 1)) S[nt][e] = -1e30f;
                }
        }

        float tm0 = fmaxf(fmaxf(S[0][0], S[0][1]), fmaxf(S[1][0], S[1][1]));
        float tm1 = fmaxf(fmaxf(S[0][2], S[0][3]), fmaxf(S[1][2], S[1][3]));
        tm0 = fmaxf(tm0, __shfl_xor_sync(0xffffffffu, tm0, 1));
        tm0 = fmaxf(tm0, __shfl_xor_sync(0xffffffffu, tm0, 2));
        tm1 = fmaxf(tm1, __shfl_xor_sync(0xffffffffu, tm1, 1));
        tm1 = fmaxf(tm1, __shfl_xor_sync(0xffffffffu, tm1, 2));
        float mn0 = fmaxf(m0, tm0), mn1 = fmaxf(m1, tm1);
        float sc0 = __expf(m0 - mn0), sc1 = __expf(m1 - mn1);
        m0 = mn0; m1 = mn1;

        float p[2][4];
#pragma unroll
        for (int nt = 0; nt < 2; nt++) {
            p[nt][0] = __expf(S[nt][0] - mn0);
            p[nt][1] = __expf(S[nt][1] - mn0);
            p[nt][2] = __expf(S[nt][2] - mn1);
            p[nt][3] = __expf(S[nt][3] - mn1);
        }
        float rs0 = p[0][0] + p[0][1] + p[1][0] + p[1][1];
        float rs1 = p[0][2] + p[0][3] + p[1][2] + p[1][3];
        rs0 += __shfl_xor_sync(0xffffffffu, rs0, 1);
        rs0 += __shfl_xor_sync(0xffffffffu, rs0, 2);
        rs1 += __shfl_xor_sync(0xffffffffu, rs1, 1);
        rs1 += __shfl_xor_sync(0xffffffffu, rs1, 2);
        l0 = l0 * sc0 + rs0;
        l1 = l1 * sc1 + rs1;

#pragma unroll
        for (int nt = 0; nt < 16; nt++) {
            O[nt][0] *= sc0; O[nt][1] *= sc0;
            O[nt][2] *= sc1; O[nt][3] *= sc1;
        }

        uint32_t pa[4], pal[4];
#pragma unroll
        for (int e = 0; e < 4; e++) {
            int nt = e >> 1, half = (e & 1) * 2;
            float v0 = p[nt][half], v1 = p[nt][half + 1];
            __nv_bfloat16 h0 = __float2bfloat16(v0);
            __nv_bfloat16 h1 = __float2bfloat16(v1);
            __nv_bfloat162 hh2{h0, h1};
            __nv_bfloat162 ll2{__float2bfloat16(v0 - __bfloat162float(h0)),
                               __float2bfloat16(v1 - __bfloat162float(h1))};
            pa[e] = *(uint32_t*)&hh2;
            pal[e] = *(uint32_t*)&ll2;
        }

#pragma unroll
        for (int j = 0; j < 8; j++) {
            uint32_t vf[4], vfl[4];
            int vg = dh * 16 + j * 2 + vb_gs;
            uint32_t vaddr = sV + vb_r * 512 + (((vg) ^ (vb_r & 7)) << 4);
            LDM4T(vf, vaddr);
            LDM4T(vfl, vaddr + 8192);
            MMA16816(O[2 * j], pa, vf[0], vf[1]);
            MMA16816(O[2 * j], pa, vfl[0], vfl[1]);
            MMA16816(O[2 * j], pal, vf[0], vf[1]);
            MMA16816(O[2 * j + 1], pa, vf[2], vf[3]);
            MMA16816(O[2 * j + 1], pa, vfl[2], vfl[3]);
            MMA16816(O[2 * j + 1], pal, vf[2], vf[3]);
        }

        if (has_next) {
            __syncthreads();                       // PV readers done; V buffer free
            stage_tile(vbh, vbl, kt + KT, sV);     // pending: [K_{i+1}, V_{i+1}]
            CPA_WAIT1;                             // K_{i+1} done
            __syncthreads();                       // K_{i+1} visible to all
        }
    }

    // ---- epilogue: normalize, split to fp16 hi/lo for the fp16 Wo GEMM
    float il0 = 1.0f / l0, il1 = 1.0f / l1;
    int row0 = Q0 + qg * 16 + (lane >> 2);
#pragma unroll
    for (int nt = 0; nt < 16; nt++) {
        int n = dh * 128 + nt * 8 + (lane & 3) * 2;
        size_t base0 = (size_t)row0 * D_MODEL + h * HD + n;
        size_t base1 = (size_t)(row0 + 8) * D_MODEL + h * HD + n;
        float v0 = O[nt][0] * il0, v1 = O[nt][1] * il0;
        float v2 = O[nt][2] * il1, v3 = O[nt][3] * il1;
        __half h0 = __float2half(v0), h1 = __float2half(v1);
        __half h2 = __float2half(v2), h3 = __float2half(v3);
        *(__half2*)(oh + base0) = __half2{h0, h1};
        *(__half2*)(oh + base1) = __half2{h2, h3};
        *(__half2*)(ol + base0) =
            __half2{__float2half(v0 - __half2float(h0)),
                    __float2half(v1 - __half2float(h1))};
        *(__half2*)(ol + base1) =
            __half2{__float2half(v2 - __half2float(h2)),
                    __float2half(v3 - __half2float(h3))};
    }
}

// ---------------------------------------------------------------------------
extern "C" void kernel_launch(void* const* d_in, const int* in_sizes, int n_in,
                              void* d_out, int out_size) {
    const float* x       = (const float*)d_in[0];
    const int* positions = (const int*)d_in[1];
    const float* Wq      = (const float*)d_in[2];
    const float* Wk      = (const float*)d_in[3];
    const float* Wv      = (const float*)d_in[4];
    const float* Wo      = (const float*)d_in[5];
    const float* q_scale = (const float*)d_in[6];
    const float* k_scale = (const float*)d_in[7];
    float* out           = (float*)d_out;

    __nv_bfloat16 *ah, *al, *wqh, *wql, *woh, *wol, *qh, *ql, *kh, *kl, *vh, *vl;
    float* qkv;
    cudaGetSymbolAddress((void**)&ah, g_ah);
    cudaGetSymbolAddress((void**)&al, g_al);
    cudaGetSymbolAddress((void**)&wqh, g_wqkv_h);
    cudaGetSymbolAddress((void**)&wql, g_wqkv_l);
    cudaGetSymbolAddress((void**)&woh, g_wo_h);
    cudaGetSymbolAddress((void**)&wol, g_wo_l);
    cudaGetSymbolAddress((void**)&qh, g_qh);
    cudaGetSymbolAddress((void**)&ql, g_ql);
    cudaGetSymbolAddress((void**)&kh, g_kh);
    cudaGetSymbolAddress((void**)&kl, g_kl);
    cudaGetSymbolAddress((void**)&vh, g_vh);
    cudaGetSymbolAddress((void**)&vl, g_vl);
    cudaGetSymbolAddress((void**)&qkv, g_qkv);

    cudaFuncSetAttribute(gemm_hmma, cudaFuncAttributeMaxDynamicSharedMemorySize,
                         GEMM_SMEM);
    cudaFuncSetAttribute(gemm_f16, cudaFuncAttributeMaxDynamicSharedMemorySize,
                         GEMM_F16_SMEM);
    cudaFuncSetAttribute(attn_tc, cudaFuncAttributeMaxDynamicSharedMemorySize,
                         ATT_SMEM);

    // fused weight transpose+split (one launch; Wo branch emits fp16)
    tsplit_all<<<dim3(160, 64), dim3(32, 8)>>>(Wq, Wk, Wv, Wo, wqh, wql, woh, wol);

    // activations: bf16 split
    int n4 = (L_SEQ * D_MODEL) / 4;
    split_kernel<<<(n4 + 255) / 256, 256>>>(x, ah, al, n4);

    // fused QKV projection (bf16x3)
    gemm_hmma<<<dim3(NQKV / 128, L_SEQ / 128), 256, GEMM_SMEM>>>(
        ah, al, wqh, wql, qkv, D_MODEL, NQKV);

    // fused norm (+rope) + split
    norm_split_all<<<dim3(L_SEQ, 12), 128>>>(qkv, q_scale, k_scale, positions,
                                             qh, ql, kh, kl, vh, vl);

    // pipelined tensor-core attention; writes fp16 split O into ah/al
    attn_tc<<<dim3(L_SEQ / QB, NH), 256, ATT_SMEM>>>(
        qh, ql, kh, kl, vh, vl, (__half*)ah, (__half*)al);

    // output projection: fp16 2-term
    gemm_f16<<<dim3(D_MODEL / 128, L_SEQ / 128), 256, GEMM_F16_SMEM>>>(
        (const __half*)ah, (const __half*)al, (const __half*)woh,
        out, D_MODEL, D_MODEL);
}

// round 17
// speedup vs baseline: 1.7659x; 1.0743x over previous
#include <cuda_runtime.h>
#include <cuda_bf16.h>
#include <cuda_fp16.h>
#include <math.h>
#include <stdint.h>

#define L_SEQ 4096
#define D_MODEL 2048
#define NH 8
#define NKVH 2
#define HD 256
#define WINDOW 512
#define NQKV 3072  // 2048 q + 512 k + 512 v

// ---------------- scratch (device globals; no cudaMalloc allowed) ----------
__device__ __nv_bfloat16 g_ah[L_SEQ * D_MODEL];        // x hi (bf16) then O hi (fp16)
__device__ __nv_bfloat16 g_al[L_SEQ * D_MODEL];        // x lo (bf16) then O lo (fp16)
__device__ __nv_bfloat16 g_wqkv_h[NQKV * D_MODEL];     // [Wq|Wk|Wv]^T hi, (N,K)
__device__ __nv_bfloat16 g_wqkv_l[NQKV * D_MODEL];
__device__ __nv_bfloat16 g_wo_h[D_MODEL * D_MODEL];    // Wo^T fp16 hi
__device__ __nv_bfloat16 g_wo_l[D_MODEL * D_MODEL];    // (unused lo, kept for layout)
__device__ float g_qkv[L_SEQ * NQKV];                  // fused qkv activations
// head-major split q/k/v for attention
__device__ __nv_bfloat16 g_qh[NH * L_SEQ * HD];
__device__ __nv_bfloat16 g_ql[NH * L_SEQ * HD];
__device__ __nv_bfloat16 g_kh[NKVH * L_SEQ * HD];
__device__ __nv_bfloat16 g_kl[NKVH * L_SEQ * HD];
__device__ __nv_bfloat16 g_vh[NKVH * L_SEQ * HD];
__device__ __nv_bfloat16 g_vl[NKVH * L_SEQ * HD];

static __device__ __forceinline__ uint32_t smem_u32(const void* p) {
    uint32_t a;
    asm("{ .reg .u64 t; cvta.to.shared.u64 t, %1; cvt.u32.u64 %0, t; }"
        : "=r"(a) : "l"(p));
    return a;
}

#define CPA16(dst, src)                                                        \
    asm volatile("cp.async.cg.shared.global [%0], [%1], 16;"                   \
                 :: "r"(dst), "l"(src) : "memory")
#define CPA_COMMIT asm volatile("cp.async.commit_group;" ::: "memory")
#define CPA_WAIT0  asm volatile("cp.async.wait_group 0;" ::: "memory")
#define CPA_WAIT1  asm volatile("cp.async.wait_group 1;" ::: "memory")

#define LDM4(r, addr)                                                          \
    asm volatile("ldmatrix.sync.aligned.m8n8.x4.shared.b16 {%0,%1,%2,%3}, [%4];"\
        : "=r"((r)[0]), "=r"((r)[1]), "=r"((r)[2]), "=r"((r)[3]) : "r"(addr))

#define LDM4T(r, addr)                                                         \
    asm volatile("ldmatrix.sync.aligned.m8n8.x4.trans.shared.b16 {%0,%1,%2,%3}, [%4];"\
        : "=r"((r)[0]), "=r"((r)[1]), "=r"((r)[2]), "=r"((r)[3]) : "r"(addr))

#define MMA16816(c, a, b0v, b1v)                                               \
    asm volatile("mma.sync.aligned.m16n8k16.row.col.f32.bf16.bf16.f32 "        \
        "{%0,%1,%2,%3}, {%4,%5,%6,%7}, {%8,%9}, {%0,%1,%2,%3};"                \
        : "+f"((c)[0]), "+f"((c)[1]), "+f"((c)[2]), "+f"((c)[3])               \
        : "r"((a)[0]), "r"((a)[1]), "r"((a)[2]), "r"((a)[3]),                  \
          "r"(b0v), "r"(b1v))

#define MMA16816F(c, a, b0v, b1v)                                              \
    asm volatile("mma.sync.aligned.m16n8k16.row.col.f32.f16.f16.f32 "          \
        "{%0,%1,%2,%3}, {%4,%5,%6,%7}, {%8,%9}, {%0,%1,%2,%3};"                \
        : "+f"((c)[0]), "+f"((c)[1]), "+f"((c)[2]), "+f"((c)[3])               \
        : "r"((a)[0]), "r"((a)[1]), "r"((a)[2]), "r"((a)[3]),                  \
          "r"(b0v), "r"(b1v))

// ---------------- split fp32 -> bf16 hi/lo (vector x4) ---------------------
__global__ void split_kernel(const float* __restrict__ in,
                             __nv_bfloat16* __restrict__ hi,
                             __nv_bfloat16* __restrict__ lo, int n4) {
    int i = blockIdx.x * blockDim.x + threadIdx.x;
    if (i >= n4) return;
    float4 a = ((const float4*)in)[i];
    __nv_bfloat16 h0 = __float2bfloat16(a.x);
    __nv_bfloat16 h1 = __float2bfloat16(a.y);
    __nv_bfloat16 h2 = __float2bfloat16(a.z);
    __nv_bfloat16 h3 = __float2bfloat16(a.w);
    __nv_bfloat16 l0 = __float2bfloat16(a.x - __bfloat162float(h0));
    __nv_bfloat16 l1 = __float2bfloat16(a.y - __bfloat162float(h1));
    __nv_bfloat16 l2 = __float2bfloat16(a.z - __bfloat162float(h2));
    __nv_bfloat16 l3 = __float2bfloat16(a.w - __bfloat162float(h3));
    __nv_bfloat162* ph = (__nv_bfloat162*)hi;
    __nv_bfloat162* pl = (__nv_bfloat162*)lo;
    ph[i * 2]     = __nv_bfloat162{h0, h1};
    ph[i * 2 + 1] = __nv_bfloat162{h2, h3};
    pl[i * 2]     = __nv_bfloat162{l0, l1};
    pl[i * 2 + 1] = __nv_bfloat162{l2, l3};
}

// ---------------- fused transpose+split of all weights ---------------------
// [0,64) Wq | [64,80) Wk | [80,96) Wv  -> bf16 hi/lo into wq buffers
// [96,160) Wo -> fp16 hi into woh (lo written but unused)
__global__ void tsplit_all(const float* __restrict__ Wq, const float* __restrict__ Wk,
                           const float* __restrict__ Wv, const float* __restrict__ Wo,
                           __nv_bfloat16* __restrict__ wqh, __nv_bfloat16* __restrict__ wql,
                           __nv_bfloat16* __restrict__ woh, __nv_bfloat16* __restrict__ wol) {
    __shared__ float s[32][33];
    int bx = blockIdx.x;
    const float* W; __nv_bfloat16 *th, *tl; int N, roff, f16 = 0;
    if (bx < 64)      { W = Wq; N = 2048; roff = 0;    th = wqh; tl = wql; }
    else if (bx < 80) { W = Wk; N = 512;  roff = 2048; th = wqh; tl = wql; bx -= 64; }
    else if (bx < 96) { W = Wv; N = 512;  roff = 2560; th = wqh; tl = wql; bx -= 80; }
    else              { W = Wo; N = 2048; roff = 0;    th = woh; tl = wol; bx -= 96; f16 = 1; }

    int n0 = bx * 32, k0 = blockIdx.y * 32;
    int tx = threadIdx.x, ty = threadIdx.y;  // 32 x 8
#pragma unroll
    for (int r = 0; r < 4; r++)
        s[ty + r * 8][tx] = W[(size_t)(k0 + ty + r * 8) * N + n0 + tx];
    __syncthreads();
#pragma unroll
    for (int r = 0; r < 4; r++) {
        int n = n0 + ty + r * 8;
        float a = s[tx][ty + r * 8];
        size_t off = (size_t)(roff + n) * D_MODEL + k0 + tx;
        if (f16) {
            __half h = __float2half(a);
            ((__half*)th)[off] = h;
            ((__half*)tl)[off] = __float2half(a - __half2float(h));
        } else {
            __nv_bfloat16 h = __float2bfloat16(a);
            th[off] = h;
            tl[off] = __float2bfloat16(a - __bfloat162float(h));
        }
    }
}

// ---------------- HMMA bf16x3 GEMM: C[M,N] = A @ B^T ------------------------
#define GOP_B 8192
#define GBUF_B (4 * GOP_B)
#define GEMM_SMEM (3 * GBUF_B)  // 96KB

#define GSW(row, g) (((row) << 6) + ((((g) ^ (((row) >> 1) & 3)) << 4)))

__global__ void __launch_bounds__(256, 2)
gemm_hmma(const __nv_bfloat16* __restrict__ Ah, const __nv_bfloat16* __restrict__ Al,
          const __nv_bfloat16* __restrict__ Bh, const __nv_bfloat16* __restrict__ Bl,
          float* __restrict__ C, int K, int ldc) {
    extern __shared__ __align__(128) char gsm[];
    const int tid = threadIdx.x;
    const int lane = tid & 31;
    const int wid = tid >> 5;
    const int wm = (wid & 1) * 64;
    const int wn = (wid >> 1) * 32;
    const int bm = blockIdx.y * 128;
    const int bn = blockIdx.x * 128;
    const uint32_t sbase = smem_u32(gsm);

    const __nv_bfloat16* gptr[4] = {
        Ah + (size_t)bm * K, Al + (size_t)bm * K,
        Bh + (size_t)bn * K, Bl + (size_t)bn * K };

    const __nv_bfloat16* srcb[8];
    uint32_t dstoff[8];
#pragma unroll
    for (int it = 0; it < 8; it++) {
        int s = it * 256 + tid;
        int op = s >> 9, t = s & 511;
        int row = t >> 2, cc = t & 3;
        srcb[it] = gptr[op] + (size_t)row * K + cc * 8;
        dstoff[it] = op * GOP_B + GSW(row, cc);
    }

    float acc[4][4][4];
#pragma unroll
    for (int a = 0; a < 4; a++)
#pragma unroll
        for (int b = 0; b < 4; b++)
#pragma unroll
            for (int c = 0; c < 4; c++) acc[a][b][c] = 0.f;

    const int a_row_l = lane & 15;
    const int a_gs = lane >> 4;
    const int b_row_l = ((lane & 16) ? 8 : 0) + (lane & 7);
    const int b_gs = (lane >> 3) & 1;

    const int nch = K >> 5;

    auto stage = [&](int c) {
        const int k0 = c << 5;
        const uint32_t dbase = sbase + (uint32_t)(c % 3) * GBUF_B;
#pragma unroll
        for (int it = 0; it < 8; it++)
            CPA16(dbase + dstoff[it], srcb[it] + k0);
        CPA_COMMIT;
    };

    stage(0);
    if (nch > 1) stage(1);

    for (int c = 0; c < nch; c++) {
        if (c + 1 < nch) { CPA_WAIT1; } else { CPA_WAIT0; }
        __syncthreads();
        if (c + 2 < nch) stage(c + 2);

        const uint32_t dbase = sbase + (uint32_t)(c % 3) * GBUF_B;
#pragma unroll
        for (int ks = 0; ks < 2; ks++) {
            const int kb2 = ks * 2;
            uint32_t bhf[2][4], blf[2][4];
#pragma unroll
            for (int np = 0; np < 2; np++) {
                int rb = wn + np * 16 + b_row_l;
                uint32_t offb = GSW(rb, kb2 + b_gs);
                LDM4(bhf[np], dbase + 2 * GOP_B + offb);
                LDM4(blf[np], dbase + 3 * GOP_B + offb);
            }
#pragma unroll
            for (int mt = 0; mt < 4; mt++) {
                uint32_t ahf[4], alf[4];
                int ra = wm + mt * 16 + a_row_l;
                uint32_t offa = GSW(ra, kb2 + a_gs);
                LDM4(ahf, dbase + offa);
                LDM4(alf, dbase + GOP_B + offa);
#pragma unroll
                for (int nt = 0; nt < 4; nt++) {
                    const int np = nt >> 1, sel = (nt & 1) * 2;
                    MMA16816(acc[mt][nt], ahf, bhf[np][sel], bhf[np][sel + 1]);
                    MMA16816(acc[mt][nt], ahf, blf[np][sel], blf[np][sel + 1]);
                    MMA16816(acc[mt][nt], alf, bhf[np][sel], bhf[np][sel + 1]);
                }
            }
        }
    }

#pragma unroll
    for (int mt = 0; mt < 4; mt++) {
        int r0 = bm + wm + mt * 16 + (lane >> 2);
#pragma unroll
        for (int nt = 0; nt < 4; nt++) {
            int c0 = bn + wn + nt * 8 + (lane & 3) * 2;
            *(float2*)(C + (size_t)r0 * ldc + c0) =
                make_float2(acc[mt][nt][0], acc[mt][nt][1]);
            *(float2*)(C + (size_t)(r0 + 8) * ldc + c0) =
                make_float2(acc[mt][nt][2], acc[mt][nt][3]);
        }
    }
}

// ---------------- HMMA fp16 2-term GEMM: C = A @ B^T ------------------------
#define FBUF_B (3 * GOP_B)        // 24KB per stage
#define GEMM_F16_SMEM (3 * FBUF_B)  // 72KB

__global__ void __launch_bounds__(256, 2)
gemm_f16(const __half* __restrict__ Ah, const __half* __restrict__ Al,
         const __half* __restrict__ Bh, float* __restrict__ C, int K, int ldc) {
    extern __shared__ __align__(128) char gsm[];
    const int tid = threadIdx.x;
    const int lane = tid & 31;
    const int wid = tid >> 5;
    const int wm = (wid & 1) * 64;
    const int wn = (wid >> 1) * 32;
    const int bm = blockIdx.y * 128;
    const int bn = blockIdx.x * 128;
    const uint32_t sbase = smem_u32(gsm);

    const __half* gptr[3] = {
        Ah + (size_t)bm * K, Al + (size_t)bm * K, Bh + (size_t)bn * K };

    const __half* srcb[6];
    uint32_t dstoff[6];
#pragma unroll
    for (int it = 0; it < 6; it++) {
        int s = it * 256 + tid;
        int op = s >> 9, t = s & 511;
        int row = t >> 2, cc = t & 3;
        srcb[it] = gptr[op] + (size_t)row * K + cc * 8;
        dstoff[it] = op * GOP_B + GSW(row, cc);
    }

    float acc[4][4][4];
#pragma unroll
    for (int a = 0; a < 4; a++)
#pragma unroll
        for (int b = 0; b < 4; b++)
#pragma unroll
            for (int c = 0; c < 4; c++) acc[a][b][c] = 0.f;

    const int a_row_l = lane & 15;
    const int a_gs = lane >> 4;
    const int b_row_l = ((lane & 16) ? 8 : 0) + (lane & 7);
    const int b_gs = (lane >> 3) & 1;

    const int nch = K >> 5;

    auto stage = [&](int c) {
        const int k0 = c << 5;
        const uint32_t dbase = sbase + (uint32_t)(c % 3) * FBUF_B;
#pragma unroll
        for (int it = 0; it < 6; it++)
            CPA16(dbase + dstoff[it], srcb[it] + k0);
        CPA_COMMIT;
    };

    stage(0);
    if (nch > 1) stage(1);

    for (int c = 0; c < nch; c++) {
        if (c + 1 < nch) { CPA_WAIT1; } else { CPA_WAIT0; }
        __syncthreads();
        if (c + 2 < nch) stage(c + 2);

        const uint32_t dbase = sbase + (uint32_t)(c % 3) * FBUF_B;
#pragma unroll
        for (int ks = 0; ks < 2; ks++) {
            const int kb2 = ks * 2;
            uint32_t bhf[2][4];
#pragma unroll
            for (int np = 0; np < 2; np++) {
                int rb = wn + np * 16 + b_row_l;
                uint32_t offb = GSW(rb, kb2 + b_gs);
                LDM4(bhf[np], dbase + 2 * GOP_B + offb);
            }
#pragma unroll
            for (int mt = 0; mt < 4; mt++) {
                uint32_t ahf[4], alf[4];
                int ra = wm + mt * 16 + a_row_l;
                uint32_t offa = GSW(ra, kb2 + a_gs);
                LDM4(ahf, dbase + offa);
                LDM4(alf, dbase + GOP_B + offa);
#pragma unroll
                for (int nt = 0; nt < 4; nt++) {
                    const int np = nt >> 1, sel = (nt & 1) * 2;
                    MMA16816F(acc[mt][nt], ahf, bhf[np][sel], bhf[np][sel + 1]);
                    MMA16816F(acc[mt][nt], alf, bhf[np][sel], bhf[np][sel + 1]);
                }
            }
        }
    }

#pragma unroll
    for (int mt = 0; mt < 4; mt++) {
        int r0 = bm + wm + mt * 16 + (lane >> 2);
#pragma unroll
        for (int nt = 0; nt < 4; nt++) {
            int c0 = bn + wn + nt * 8 + (lane & 3) * 2;
            *(float2*)(C + (size_t)r0 * ldc + c0) =
                make_float2(acc[mt][nt][0], acc[mt][nt][1]);
            *(float2*)(C + (size_t)(r0 + 8) * ldc + c0) =
                make_float2(acc[mt][nt][2], acc[mt][nt][3]);
        }
    }
}

// ---------------- fused RMS norm (+scale, +RoPE) -> split bf16 head-major --
#define LOG2_BASE 13.287712379549449f
#define INV_2PI   0.15915494309189535f
#define C1_2PI    6.2831855f
#define C2_2PI   -1.7484555e-7f

__global__ void norm_split_all(const float* __restrict__ qkv,
                               const float* __restrict__ q_scale,
                               const float* __restrict__ k_scale,
                               const int* __restrict__ positions,
                               __nv_bfloat16* __restrict__ qh, __nv_bfloat16* __restrict__ ql,
                               __nv_bfloat16* __restrict__ kh, __nv_bfloat16* __restrict__ kl,
                               __nv_bfloat16* __restrict__ vh, __nv_bfloat16* __restrict__ vl) {
    const int l = blockIdx.x;
    const int slot = blockIdx.y;   // 0..11
    int headoff, hh, do_rope;
    const float* scale;
    __nv_bfloat16 *oh, *ol;
    if (slot < 8)       { headoff = 0;    hh = slot;      scale = q_scale; do_rope = 1; oh = qh; ol = ql; }
    else if (slot < 10) { headoff = 2048; hh = slot - 8;  scale = k_scale; do_rope = 1; oh = kh; ol = kl; }
    else                { headoff = 2560; hh = slot - 10; scale = nullptr; do_rope = 0; oh = vh; ol = vl; }

    const float* p = qkv + (size_t)l * NQKV + headoff + hh * HD;
    const int t = threadIdx.x;  // 0..127
    const int lane = t & 31;
    const int wid = t >> 5;

    float a = p[t];
    float b = p[t + 128];
    float ss = a * a + b * b;
#pragma unroll
    for (int off = 16; off > 0; off >>= 1)
        ss += __shfl_xor_sync(0xffffffffu, ss, off);
    __shared__ float red4[4];
    if (lane == 0) red4[wid] = ss;
    __syncthreads();
    float total = red4[0] + red4[1] + red4[2] + red4[3];
    float inv = rsqrtf(total * (1.0f / HD) + 1e-6f);

    float xa = a * inv, xb = b * inv;
    if (scale) { xa *= scale[t]; xb *= scale[t + 128]; }

    float ya, yb;
    if (do_rope) {
        float pos = (float)positions[l];
        float inv_ts = exp2f(-(2.0f * (float)t / (float)HD) * LOG2_BASE);
        float ang = pos * inv_ts;
        float n = rintf(ang * INV_2PI);
        float r = fmaf(-n, C1_2PI, ang);
        r = fmaf(-n, C2_2PI, r);
        float sn = __sinf(r);
        float cs = __cosf(r);
        ya = xa * cs - xb * sn;
        yb = xb * cs + xa * sn;
    } else {
        ya = xa; yb = xb;
    }
    size_t o = ((size_t)hh * L_SEQ + l) * HD;
    __nv_bfloat16 ha = __float2bfloat16(ya);
    __nv_bfloat16 hb = __float2bfloat16(yb);
    oh[o + t]       = ha;
    oh[o + t + 128] = hb;
    ol[o + t]       = __float2bfloat16(ya - __bfloat162float(ha));
    ol[o + t + 128] = __float2bfloat16(yb - __bfloat162float(hb));
}

// ---------------- tensor-core sliding-window flash attention ---------------
// Pipelined K (double-buffer) / V (single) staging; 112KB smem, 2 CTAs/SM.
// S-dedup: each d-half warp accumulates half the d-reduction (48 MMAs),
// partials exchanged through the dead K buffer after the post-S barrier.
#define QB 64
#define KT 16
#define ATT_SMEM (112 * 1024)

__global__ void __launch_bounds__(256, 2)
attn_tc(const __nv_bfloat16* __restrict__ qhp, const __nv_bfloat16* __restrict__ qlp,
        const __nv_bfloat16* __restrict__ khp, const __nv_bfloat16* __restrict__ klp,
        const __nv_bfloat16* __restrict__ vhp, const __nv_bfloat16* __restrict__ vlp,
        __half* __restrict__ oh, __half* __restrict__ ol) {
    extern __shared__ __align__(128) char asmem[];
    const int tid = threadIdx.x, lane = tid & 31, wid = tid >> 5;
    const int qb = blockIdx.x, h = blockIdx.y;
    const int kvh = h / (NH / NKVH);
    const int Q0 = qb * QB;
    const int qg = wid >> 1;
    const int dh = wid & 1;
    const uint32_t sb = smem_u32(asmem);
    const uint32_t sQ = sb;                     // hi; lo at +32768
    const uint32_t sK = sb + 65536;             // buf b at + b*16384 (Kh | Kl+8192)
    const uint32_t sV = sb + 98304;             // Vh | Vl+8192

    const __nv_bfloat16* kbh = khp + (size_t)kvh * L_SEQ * HD;
    const __nv_bfloat16* kbl = klp + (size_t)kvh * L_SEQ * HD;
    const __nv_bfloat16* vbh = vhp + (size_t)kvh * L_SEQ * HD;
    const __nv_bfloat16* vbl = vlp + (size_t)kvh * L_SEQ * HD;

    auto stage_tile = [&](const __nv_bfloat16* mh, const __nv_bfloat16* ml,
                          int kt, uint32_t dbase) {
#pragma unroll
        for (int r = 0; r < 4; r++) {
            int gid = r * 256 + tid;
            int mat = gid >> 9;
            int t = gid & 511;
            int row = t >> 5, g = t & 31;
            const __nv_bfloat16* src = (mat ? ml : mh) + (size_t)(kt + row) * HD + g * 8;
            uint32_t dst = dbase + mat * 8192 + row * 512 + ((g ^ (row & 7)) << 4);
            CPA16(dst, src);
        }
        CPA_COMMIT;
    };

    // ---- stage Q, then K0, then V0 (three groups)
#pragma unroll
    for (int i = 0; i < 16; i++) {
        int gid = i * 256 + tid;
        int mat = gid >> 11;
        int t = gid & 2047;
        int row = t >> 5, g = t & 31;
        const __nv_bfloat16* src = (mat ? qlp : qhp)
            + ((size_t)h * L_SEQ + Q0 + row) * HD + g * 8;
        uint32_t dst = sQ + mat * 32768 + row * 512 + ((g ^ (row & 7)) << 4);
        CPA16(dst, src);
    }
    CPA_COMMIT;

    int kstart = Q0 - (WINDOW - 1);
    if (kstart < 0) kstart = 0;
    kstart &= ~(KT - 1);
    const int kend = Q0 + QB;
    const int R0 = Q0 + qg * 16;

    stage_tile(kbh, kbl, kstart, sK);       // K0 -> buf 0
    stage_tile(vbh, vbl, kstart, sV);       // V0
    CPA_WAIT0;
    __syncthreads();

    float m0 = -1e9f, m1 = -1e9f;
    float l0 = 0.f, l1 = 0.f;
    float O[16][4];
#pragma unroll
    for (int nt = 0; nt < 16; nt++)
#pragma unroll
        for (int e = 0; e < 4; e++) O[nt][e] = 0.f;

    const int qa_r = ((lane >> 3) & 1) * 8 + (lane & 7);
    const int qa_gs = (lane >> 4);
    const int kb_r = ((lane >> 4) & 1) * 8 + (lane & 7);
    const int kb_gs = ((lane >> 3) & 1);
    const int vb_r = ((lane >> 3) & 1) * 8 + (lane & 7);
    const int vb_gs = (lane >> 4);

    int buf = 0;
    for (int kt = kstart; kt < kend; kt += KT, buf ^= 1) {
        const bool has_next = (kt + KT < kend);
        const uint32_t kB = sK + buf * 16384;

        // ---- partial S over this warp's d-half (ks = dh*8 .. dh*8+7)
        float S[2][4];
#pragma unroll
        for (int nt = 0; nt < 2; nt++)
#pragma unroll
            for (int e = 0; e < 4; e++) S[nt][e] = 0.f;

#pragma unroll
        for (int ks = 0; ks < 8; ks++) {
            const int ks2 = dh * 8 + ks;
            uint32_t qa[4], qal[4], kf[4], kfl[4];
            int qrow = qg * 16 + qa_r;
            int qg_g = ks2 * 2 + qa_gs;
            uint32_t qaddr = sQ + qrow * 512 + (((qg_g) ^ (qrow & 7)) << 4);
            LDM4(qa, qaddr);
            LDM4(qal, qaddr + 32768);
            int kg_g = ks2 * 2 + kb_gs;
            uint32_t kaddr = kB + kb_r * 512 + (((kg_g) ^ (kb_r & 7)) << 4);
            LDM4(kf, kaddr);
            LDM4(kfl, kaddr + 8192);
            MMA16816(S[0], qa, kf[0], kf[1]);
            MMA16816(S[0], qa, kfl[0], kfl[1]);
            MMA16816(S[0], qal, kf[0], kf[1]);
            MMA16816(S[1], qa, kf[2], kf[3]);
            MMA16816(S[1], qa, kfl[2], kfl[3]);
            MMA16816(S[1], qal, kf[2], kf[3]);
        }

        if (has_next) stage_tile(kbh, kbl, kt + KT, sK + (buf ^ 1) * 16384);

        if (has_next) { CPA_WAIT1; } else { CPA_WAIT0; }
        __syncthreads();   // all S reads of kB done; K_{i+1} visible

        // ---- exchange partial S through the dead current-K buffer
        {
            char* xown = asmem + (kB - sb) + ((qg * 2 + dh) << 10) + lane * 32;
            *(float4*)xown       = make_float4(S[0][0], S[0][1], S[0][2], S[0][3]);
            *(float4*)(xown + 16) = make_float4(S[1][0], S[1][1], S[1][2], S[1][3]);
        }
        __syncthreads();
        {
            const char* xpar = asmem + (kB - sb) + ((qg * 2 + (dh ^ 1)) << 10) + lane * 32;
            float4 p0 = *(const float4*)xpar;
            float4 p1 = *(const float4*)(xpar + 16);
            S[0][0] += p0.x; S[0][1] += p0.y; S[0][2] += p0.z; S[0][3] += p0.w;
            S[1][0] += p1.x; S[1][1] += p1.y; S[1][2] += p1.z; S[1][3] += p1.w;
        }

        const bool fullvalid = (kt + KT - 1 <= R0) && (kt >= R0 + 15 - (WINDOW - 1));
        if (!fullvalid) {
            int rq0 = R0 + (lane >> 2);
            int ck = kt + (lane & 3) * 2;
#pragma unroll
            for (int nt = 0; nt < 2; nt++)
#pragma unroll
                for (int e = 0; e < 4; e++) {
                    int q = rq0 + ((e >= 2) ? 8 : 0);
                    int k = ck + nt * 8 + (e & 1);
                    if (k > q || k < q - (WINDOW - 1)) S[nt][e] = -1e30f;
                }
        }

        float tm0 = fmaxf(fmaxf(S[0][0], S[0][1]), fmaxf(S[1][0], S[1][1]));
        float tm1 = fmaxf(fmaxf(S[0][2], S[0][3]), fmaxf(S[1][2], S[1][3]));
        tm0 = fmaxf(tm0, __shfl_xor_sync(0xffffffffu, tm0, 1));
        tm0 = fmaxf(tm0, __shfl_xor_sync(0xffffffffu, tm0, 2));
        tm1 = fmaxf(tm1, __shfl_xor_sync(0xffffffffu, tm1, 1));
        tm1 = fmaxf(tm1, __shfl_xor_sync(0xffffffffu, tm1, 2));
        float mn0 = fmaxf(m0, tm0), mn1 = fmaxf(m1, tm1);
        float sc0 = __expf(m0 - mn0), sc1 = __expf(m1 - mn1);
        m0 = mn0; m1 = mn1;

        float p[2][4];
#pragma unroll
        for (int nt = 0; nt < 2; nt++) {
            p[nt][0] = __expf(S[nt][0] - mn0);
            p[nt][1] = __expf(S[nt][1] - mn0);
            p[nt][2] = __expf(S[nt][2] - mn1);
            p[nt][3] = __expf(S[nt][3] - mn1);
        }
        float rs0 = p[0][0] + p[0][1] + p[1][0] + p[1][1];
        float rs1 = p[0][2] + p[0][3] + p[1][2] + p[1][3];
        rs0 += __shfl_xor_sync(0xffffffffu, rs0, 1);
        rs0 += __shfl_xor_sync(0xffffffffu, rs0, 2);
        rs1 += __shfl_xor_sync(0xffffffffu, rs1, 1);
        rs1 += __shfl_xor_sync(0xffffffffu, rs1, 2);
        l0 = l0 * sc0 + rs0;
        l1 = l1 * sc1 + rs1;

#pragma unroll
        for (int nt = 0; nt < 16; nt++) {
            O[nt][0] *= sc0; O[nt][1] *= sc0;
            O[nt][2] *= sc1; O[nt][3] *= sc1;
        }

        uint32_t pa[4], pal[4];
#pragma unroll
        for (int e = 0; e < 4; e++) {
            int nt = e >> 1, half = (e & 1) * 2;
            float v0 = p[nt][half], v1 = p[nt][half + 1];
            __nv_bfloat16 h0 = __float2bfloat16(v0);
            __nv_bfloat16 h1 = __float2bfloat16(v1);
            __nv_bfloat162 hh2{h0, h1};
            __nv_bfloat162 ll2{__float2bfloat16(v0 - __bfloat162float(h0)),
                               __float2bfloat16(v1 - __bfloat162float(h1))};
            pa[e] = *(uint32_t*)&hh2;
            pal[e] = *(uint32_t*)&ll2;
        }

#pragma unroll
        for (int j = 0; j < 8; j++) {
            uint32_t vf[4], vfl[4];
            int vg = dh * 16 + j * 2 + vb_gs;
            uint32_t vaddr = sV + vb_r * 512 + (((vg) ^ (vb_r & 7)) << 4);
            LDM4T(vf, vaddr);
            LDM4T(vfl, vaddr + 8192);
            MMA16816(O[2 * j], pa, vf[0], vf[1]);
            MMA16816(O[2 * j], pa, vfl[0], vfl[1]);
            MMA16816(O[2 * j], pal, vf[0], vf[1]);
            MMA16816(O[2 * j + 1], pa, vf[2], vf[3]);
            MMA16816(O[2 * j + 1], pa, vfl[2], vfl[3]);
            MMA16816(O[2 * j + 1], pal, vf[2], vf[3]);
        }

        if (has_next) {
            __syncthreads();                       // PV readers done; V buffer free
            stage_tile(vbh, vbl, kt + KT, sV);     // pending: [K_{i+1}, V_{i+1}]
            CPA_WAIT1;                             // K_{i+1} done
            __syncthreads();                       // K_{i+1} visible to all
        }
    }

    // ---- epilogue: normalize, split to fp16 hi/lo for the fp16 Wo GEMM
    float il0 = 1.0f / l0, il1 = 1.0f / l1;
    int row0 = Q0 + qg * 16 + (lane >> 2);
#pragma unroll
    for (int nt = 0; nt < 16; nt++) {
        int n = dh * 128 + nt * 8 + (lane & 3) * 2;
        size_t base0 = (size_t)row0 * D_MODEL + h * HD + n;
        size_t base1 = (size_t)(row0 + 8) * D_MODEL + h * HD + n;
        float v0 = O[nt][0] * il0, v1 = O[nt][1] * il0;
        float v2 = O[nt][2] * il1, v3 = O[nt][3] * il1;
        __half h0 = __float2half(v0), h1 = __float2half(v1);
        __half h2 = __float2half(v2), h3 = __float2half(v3);
        *(__half2*)(oh + base0) = __half2{h0, h1};
        *(__half2*)(oh + base1) = __half2{h2, h3};
        *(__half2*)(ol + base0) =
            __half2{__float2half(v0 - __half2float(h0)),
                    __float2half(v1 - __half2float(h1))};
        *(__half2*)(ol + base1) =
            __half2{__float2half(v2 - __half2float(h2)),
                    __float2half(v3 - __half2float(h3))};
    }
}

// ---------------------------------------------------------------------------
extern "C" void kernel_launch(void* const* d_in, const int* in_sizes, int n_in,
                              void* d_out, int out_size) {
    const float* x       = (const float*)d_in[0];
    const int* positions = (const int*)d_in[1];
    const float* Wq      = (const float*)d_in[2];
    const float* Wk      = (const float*)d_in[3];
    const float* Wv      = (const float*)d_in[4];
    const float* Wo      = (const float*)d_in[5];
    const float* q_scale = (const float*)d_in[6];
    const float* k_scale = (const float*)d_in[7];
    float* out           = (float*)d_out;

    __nv_bfloat16 *ah, *al, *wqh, *wql, *woh, *wol, *qh, *ql, *kh, *kl, *vh, *vl;
    float* qkv;
    cudaGetSymbolAddress((void**)&ah, g_ah);
    cudaGetSymbolAddress((void**)&al, g_al);
    cudaGetSymbolAddress((void**)&wqh, g_wqkv_h);
    cudaGetSymbolAddress((void**)&wql, g_wqkv_l);
    cudaGetSymbolAddress((void**)&woh, g_wo_h);
    cudaGetSymbolAddress((void**)&wol, g_wo_l);
    cudaGetSymbolAddress((void**)&qh, g_qh);
    cudaGetSymbolAddress((void**)&ql, g_ql);
    cudaGetSymbolAddress((void**)&kh, g_kh);
    cudaGetSymbolAddress((void**)&kl, g_kl);
    cudaGetSymbolAddress((void**)&vh, g_vh);
    cudaGetSymbolAddress((void**)&vl, g_vl);
    cudaGetSymbolAddress((void**)&qkv, g_qkv);

    cudaFuncSetAttribute(gemm_hmma, cudaFuncAttributeMaxDynamicSharedMemorySize,
                         GEMM_SMEM);
    cudaFuncSetAttribute(gemm_f16, cudaFuncAttributeMaxDynamicSharedMemorySize,
                         GEMM_F16_SMEM);
    cudaFuncSetAttribute(attn_tc, cudaFuncAttributeMaxDynamicSharedMemorySize,
                         ATT_SMEM);

    // fused weight transpose+split (one launch; Wo branch emits fp16)
    tsplit_all<<<dim3(160, 64), dim3(32, 8)>>>(Wq, Wk, Wv, Wo, wqh, wql, woh, wol);

    // activations: bf16 split
    int n4 = (L_SEQ * D_MODEL) / 4;
    split_kernel<<<(n4 + 255) / 256, 256>>>(x, ah, al, n4);

    // fused QKV projection (bf16x3)
    gemm_hmma<<<dim3(NQKV / 128, L_SEQ / 128), 256, GEMM_SMEM>>>(
        ah, al, wqh, wql, qkv, D_MODEL, NQKV);

    // fused norm (+rope) + split
    norm_split_all<<<dim3(L_SEQ, 12), 128>>>(qkv, q_scale, k_scale, positions,
                                             qh, ql, kh, kl, vh, vl);

    // pipelined tensor-core attention (S-dedup); writes fp16 split O into ah/al
    attn_tc<<<dim3(L_SEQ / QB, NH), 256, ATT_SMEM>>>(
        qh, ql, kh, kl, vh, vl, (__half*)ah, (__half*)al);

    // output projection: fp16 2-term
    gemm_f16<<<dim3(D_MODEL / 128, L_SEQ / 128), 256, GEMM_F16_SMEM>>>(
        (const __half*)ah, (const __half*)al, (const __half*)woh,
        out, D_MODEL, D_MODEL);
}